// round 1
// baseline (speedup 1.0000x reference)
#include <cuda_runtime.h>
#include <math.h>

#define NTOK 16384
#define CDIM 256
#define HID  1024
#define NHEAD 8

// -------- scratch (no allocations allowed; __device__ globals) --------
__device__ float g_xn  [NTOK * CDIM];
__device__ float g_v   [NTOK * CDIM];
__device__ float g_off [NTOK * 144];
__device__ float g_attn[NTOK * 72];
__device__ float g_agg [NTOK * CDIM];
__device__ float g_xres[NTOK * CDIM];
__device__ float g_y   [NTOK * CDIM];
__device__ float g_h   [NTOK * HID];
__device__ float g_h2  [NTOK * HID];

__device__ __forceinline__ float gelu_f(float v) {
    return 0.5f * v * (1.0f + erff(v * 0.7071067811865476f));
}

// ---------------- LayerNorm: one block (256 threads) per token ----------------
__global__ void ln_kernel(const float* __restrict__ x, const float* __restrict__ g,
                          const float* __restrict__ b, float* __restrict__ y) {
    int tok = blockIdx.x;
    int c = threadIdx.x;
    float v = x[(size_t)tok * CDIM + c];
    __shared__ float sh[8];
    float s = v;
    #pragma unroll
    for (int o = 16; o; o >>= 1) s += __shfl_xor_sync(0xffffffffu, s, o);
    if ((c & 31) == 0) sh[c >> 5] = s;
    __syncthreads();
    float tot = 0.f;
    #pragma unroll
    for (int i = 0; i < 8; ++i) tot += sh[i];
    float mean = tot * (1.0f / CDIM);
    __syncthreads();
    float d = v - mean;
    float s2 = d * d;
    #pragma unroll
    for (int o = 16; o; o >>= 1) s2 += __shfl_xor_sync(0xffffffffu, s2, o);
    if ((c & 31) == 0) sh[c >> 5] = s2;
    __syncthreads();
    float v2 = 0.f;
    #pragma unroll
    for (int i = 0; i < 8; ++i) v2 += sh[i];
    float var = v2 * (1.0f / CDIM);
    y[(size_t)tok * CDIM + c] = d * rsqrtf(var + 1e-5f) * g[c] + b[c];
}

// ---------------- SGEMM: C[M,N] = A[M,K] @ B[K,N] + bias (+resid) (opt gelu) ----
// BM=128, BN=64, BK=16, 256 threads, 8x4 per-thread tile.
#define BM 128
#define BN 64
#define BKK 16

template<bool GELU>
__global__ __launch_bounds__(256)
void sgemm_kernel(const float* __restrict__ A, const float* __restrict__ Bw,
                  const float* __restrict__ bias, const float* __restrict__ resid,
                  float* __restrict__ C, int M, int N, int Kd) {
    __shared__ float As[BKK][BM];
    __shared__ float Bs[BKK][BN];
    int t = threadIdx.x;
    int tx = t & 15;        // 0..15 -> 4 cols each
    int ty = t >> 4;        // 0..15 -> 8 rows each
    int m0 = blockIdx.y * BM;
    int n0 = blockIdx.x * BN;

    int ar = t >> 2;            // A-tile row (0..63), second row = +64
    int ak = (t & 3) * 4;       // A-tile k offset
    int brow = t >> 4;          // B-tile row (0..15)
    int bc4 = (t & 15) * 4;     // B-tile col offset

    float acc[8][4];
    #pragma unroll
    for (int i = 0; i < 8; ++i)
        #pragma unroll
        for (int j = 0; j < 4; ++j) acc[i][j] = 0.f;

    for (int k0 = 0; k0 < Kd; k0 += BKK) {
        float4 a0 = *(const float4*)(A + (size_t)(m0 + ar) * Kd + k0 + ak);
        float4 a1 = *(const float4*)(A + (size_t)(m0 + ar + 64) * Kd + k0 + ak);
        float4 bv;
        if (n0 + bc4 + 4 <= N) {
            bv = *(const float4*)(Bw + (size_t)(k0 + brow) * N + n0 + bc4);
        } else {
            const float* bp = Bw + (size_t)(k0 + brow) * N;
            bv.x = (n0 + bc4 + 0 < N) ? bp[n0 + bc4 + 0] : 0.f;
            bv.y = (n0 + bc4 + 1 < N) ? bp[n0 + bc4 + 1] : 0.f;
            bv.z = (n0 + bc4 + 2 < N) ? bp[n0 + bc4 + 2] : 0.f;
            bv.w = (n0 + bc4 + 3 < N) ? bp[n0 + bc4 + 3] : 0.f;
        }
        __syncthreads();
        As[ak + 0][ar] = a0.x; As[ak + 1][ar] = a0.y;
        As[ak + 2][ar] = a0.z; As[ak + 3][ar] = a0.w;
        As[ak + 0][ar + 64] = a1.x; As[ak + 1][ar + 64] = a1.y;
        As[ak + 2][ar + 64] = a1.z; As[ak + 3][ar + 64] = a1.w;
        Bs[brow][bc4 + 0] = bv.x; Bs[brow][bc4 + 1] = bv.y;
        Bs[brow][bc4 + 2] = bv.z; Bs[brow][bc4 + 3] = bv.w;
        __syncthreads();
        #pragma unroll
        for (int kk = 0; kk < BKK; ++kk) {
            float4 af0 = *(const float4*)&As[kk][ty * 8];
            float4 af1 = *(const float4*)&As[kk][ty * 8 + 4];
            float4 bf  = *(const float4*)&Bs[kk][tx * 4];
            float a[8] = {af0.x, af0.y, af0.z, af0.w, af1.x, af1.y, af1.z, af1.w};
            float bb[4] = {bf.x, bf.y, bf.z, bf.w};
            #pragma unroll
            for (int i = 0; i < 8; ++i)
                #pragma unroll
                for (int j = 0; j < 4; ++j)
                    acc[i][j] += a[i] * bb[j];
        }
    }

    #pragma unroll
    for (int i = 0; i < 8; ++i) {
        int row = m0 + ty * 8 + i;
        #pragma unroll
        for (int j = 0; j < 4; ++j) {
            int col = n0 + tx * 4 + j;
            if (col < N) {
                float val = acc[i][j] + bias[col];
                if (resid) val += resid[(size_t)row * N + col];
                if (GELU)  val = gelu_f(val);
                C[(size_t)row * N + col] = val;
            }
        }
    }
}

// ---------------- Deformable sampling + softmax + aggregation ----------------
// One warp per (token, head); lane = channel within head (HD=32).
__global__ void sample_kernel(const float* __restrict__ v, const float* __restrict__ off,
                              const float* __restrict__ logits, const float* __restrict__ rp,
                              float* __restrict__ agg) {
    int gw = blockIdx.x * 8 + (threadIdx.x >> 5);
    int lane = threadIdx.x & 31;
    int head = gw & 7;
    int tg = gw >> 3;           // global token (b*8192 + y*128 + x)
    int bb = tg >> 13;
    int pos = tg & 8191;

    const float* lg = logits + (size_t)tg * 72 + head * 9;
    float w[9];
    float mx = -1e30f;
    #pragma unroll
    for (int k = 0; k < 9; ++k) { w[k] = lg[k]; mx = fmaxf(mx, w[k]); }
    float sum = 0.f;
    #pragma unroll
    for (int k = 0; k < 9; ++k) { w[k] = expf(w[k] - mx); sum += w[k]; }
    float inv = 1.0f / sum;

    const float* rpp  = rp + (size_t)pos * 18;          // ref_point (broadcast over B)
    const float* offp = off + (size_t)tg * 144 + head * 18;
    const float* vc   = v + head * 32 + lane;
    int base = bb << 13;
    float acc = 0.f;
    #pragma unroll
    for (int k = 0; k < 9; ++k) {
        float cx = (rpp[k * 2 + 0] + offp[k * 2 + 0] + 1.0f) * 0.5f * 127.0f;
        float cy = (rpp[k * 2 + 1] + offp[k * 2 + 1] + 1.0f) * 0.5f * 63.0f;
        float fx = floorf(cx), fy = floorf(cy);
        float wx = cx - fx, wy = cy - fy;
        int x0 = min(max((int)fx, 0), 127);
        int x1 = min(max((int)fx + 1, 0), 127);
        int y0 = min(max((int)fy, 0), 63);
        int y1 = min(max((int)fy + 1, 0), 63);
        float v00 = vc[(size_t)(base + y0 * 128 + x0) * 256];
        float v01 = vc[(size_t)(base + y0 * 128 + x1) * 256];
        float v10 = vc[(size_t)(base + y1 * 128 + x0) * 256];
        float v11 = vc[(size_t)(base + y1 * 128 + x1) * 256];
        float s = v00 * (1.f - wy) * (1.f - wx) + v01 * (1.f - wy) * wx
                + v10 * wy * (1.f - wx) + v11 * wy * wx;
        acc += s * (w[k] * inv);
    }
    agg[(size_t)tg * 256 + head * 32 + lane] = acc;
}

// ---------------- Depthwise 3x3 conv (circular W, zero H) + bias + GELU ------
__global__ void dwconv_kernel(const float* __restrict__ h, const float* __restrict__ wdw,
                              const float* __restrict__ bdw, float* __restrict__ o) {
    int c = blockIdx.x * 256 + threadIdx.x;   // 0..1023
    int tok = blockIdx.y;                      // 0..16383
    int bb = tok >> 13;
    int y = (tok >> 7) & 63;
    int x = tok & 127;
    float acc = bdw[c];
    #pragma unroll
    for (int dy = -1; dy <= 1; ++dy) {
        int yy = y + dy;
        if (yy < 0 || yy > 63) continue;
        int rowbase = (bb << 13) + (yy << 7);
        #pragma unroll
        for (int dx = -1; dx <= 1; ++dx) {
            int xx = (x + dx + 128) & 127;     // circular width
            acc += h[(size_t)(rowbase + xx) * HID + c]
                 * wdw[c * 9 + (dy + 1) * 3 + (dx + 1)];
        }
    }
    o[(size_t)tok * HID + c] = gelu_f(acc);
}

// ---------------- launch ----------------
extern "C" void kernel_launch(void* const* d_in, const int* in_sizes, int n_in,
                              void* d_out, int out_size) {
    const float* x      = (const float*)d_in[0];
    const float* rp     = (const float*)d_in[1];
    const float* ln1_g  = (const float*)d_in[2];
    const float* ln1_b  = (const float*)d_in[3];
    const float* w_v    = (const float*)d_in[4];
    const float* b_v    = (const float*)d_in[5];
    const float* w_off  = (const float*)d_in[6];
    const float* b_off  = (const float*)d_in[7];
    const float* w_attn = (const float*)d_in[8];
    const float* b_attn = (const float*)d_in[9];
    const float* w_out  = (const float*)d_in[10];
    const float* b_out  = (const float*)d_in[11];
    const float* ln2_g  = (const float*)d_in[12];
    const float* ln2_b  = (const float*)d_in[13];
    const float* w1     = (const float*)d_in[14];
    const float* b1     = (const float*)d_in[15];
    const float* w_dw   = (const float*)d_in[16];
    const float* b_dw   = (const float*)d_in[17];
    const float* w2     = (const float*)d_in[18];
    const float* b2     = (const float*)d_in[19];
    float* out = (float*)d_out;

    float *xn, *v, *off, *attn, *agg, *xres, *y, *h, *h2;
    cudaGetSymbolAddress((void**)&xn,   g_xn);
    cudaGetSymbolAddress((void**)&v,    g_v);
    cudaGetSymbolAddress((void**)&off,  g_off);
    cudaGetSymbolAddress((void**)&attn, g_attn);
    cudaGetSymbolAddress((void**)&agg,  g_agg);
    cudaGetSymbolAddress((void**)&xres, g_xres);
    cudaGetSymbolAddress((void**)&y,    g_y);
    cudaGetSymbolAddress((void**)&h,    g_h);
    cudaGetSymbolAddress((void**)&h2,   g_h2);

    // 1. LN1
    ln_kernel<<<NTOK, 256>>>(x, ln1_g, ln1_b, xn);
    // 2-4. projections
    sgemm_kernel<false><<<dim3(256 / BN, NTOK / BM), 256>>>(xn, w_v,    b_v,    nullptr, v,    NTOK, 256,  256);
    sgemm_kernel<false><<<dim3((144 + BN - 1) / BN, NTOK / BM), 256>>>(xn, w_off,  b_off,  nullptr, off,  NTOK, 144,  256);
    sgemm_kernel<false><<<dim3((72 + BN - 1) / BN, NTOK / BM), 256>>>(xn, w_attn, b_attn, nullptr, attn, NTOK, 72,   256);
    // 5. softmax + bilinear sampling + aggregation
    sample_kernel<<<NTOK, 256>>>(v, off, attn, rp, agg);
    // 6. output proj + residual
    sgemm_kernel<false><<<dim3(256 / BN, NTOK / BM), 256>>>(agg, w_out, b_out, x, xres, NTOK, 256, 256);
    // 7. LN2
    ln_kernel<<<NTOK, 256>>>(xres, ln2_g, ln2_b, y);
    // 8. fc1 + GELU
    sgemm_kernel<true><<<dim3(HID / BN, NTOK / BM), 256>>>(y, w1, b1, nullptr, h, NTOK, HID, 256);
    // 9. depthwise conv + GELU
    dwconv_kernel<<<dim3(HID / 256, NTOK), 256>>>(h, w_dw, b_dw, h2);
    // 10. fc2 + residual -> out
    sgemm_kernel<false><<<dim3(256 / BN, NTOK / BM), 256>>>(h2, w2, b2, xres, out, NTOK, 256, HID);
}

// round 2
// speedup vs baseline: 2.0855x; 2.0855x over previous
#include <cuda_runtime.h>
#include <cuda_bf16.h>
#include <math.h>
#include <stdint.h>

typedef __nv_bfloat16 bf16;

#define NTOK 16384
#define CDIM 256
#define HID  1024

// -------- scratch (__device__ globals; no allocations allowed) --------
__device__ float g_xn     [NTOK * CDIM];
__device__ float g_offattn[NTOK * 216];
__device__ float g_xres   [NTOK * CDIM];
__device__ bf16  g_xnb    [NTOK * CDIM];
__device__ bf16  g_vb     [NTOK * CDIM];
__device__ bf16  g_aggb   [NTOK * CDIM];
__device__ bf16  g_yb     [NTOK * CDIM];
__device__ bf16  g_hb     [NTOK * HID];
__device__ bf16  g_h2b    [NTOK * HID];
__device__ bf16  g_wvb    [256 * 256];
__device__ bf16  g_woutb  [256 * 256];
__device__ bf16  g_w1b    [256 * 1024];
__device__ bf16  g_w2b    [1024 * 256];
__device__ float g_wcat   [256 * 216];
__device__ float g_bcat   [216];

__device__ __forceinline__ float gelu_f(float v) {
    return 0.5f * v * (1.0f + erff(v * 0.7071067811865476f));
}

__device__ __forceinline__ uint32_t smem_u32(const void* p) {
    uint32_t a;
    asm("{ .reg .u64 t; cvta.to.shared.u64 t, %1; cvt.u32.u64 %0, t; }" : "=r"(a) : "l"(p));
    return a;
}

// ---------------- weight conversions: one kernel, segmented -------------------
__global__ void f2bf_all_kernel(const float* wv, const float* wout, const float* w1,
                                const float* w2, bf16* wvb, bf16* woutb, bf16* w1b, bf16* w2b) {
    int i = blockIdx.x * 256 + threadIdx.x;
    // segments: 65536 | 65536 | 262144 | 262144
    if (i < 65536) { wvb[i] = __float2bfloat16(wv[i]); return; }
    i -= 65536;
    if (i < 65536) { woutb[i] = __float2bfloat16(wout[i]); return; }
    i -= 65536;
    if (i < 262144) { w1b[i] = __float2bfloat16(w1[i]); return; }
    i -= 262144;
    if (i < 262144) { w2b[i] = __float2bfloat16(w2[i]); return; }
}

__global__ void wcat_kernel(const float* w_off, const float* w_attn,
                            const float* b_off, const float* b_attn,
                            float* wcat, float* bcat) {
    int i = blockIdx.x * 256 + threadIdx.x;
    if (i < 256 * 216) {
        int k = i / 216, j = i % 216;
        wcat[i] = (j < 144) ? w_off[k * 144 + j] : w_attn[k * 72 + (j - 144)];
    }
    if (i < 216) bcat[i] = (i < 144) ? b_off[i] : b_attn[i - 144];
}

// ---------------- LayerNorm: one block per token, dual output ----------------
__global__ void ln_kernel(const float* __restrict__ x, const float* __restrict__ g,
                          const float* __restrict__ b, float* __restrict__ yf,
                          bf16* __restrict__ yb) {
    int tok = blockIdx.x;
    int c = threadIdx.x;
    float v = x[(size_t)tok * CDIM + c];
    __shared__ float sh[8];
    float s = v;
    #pragma unroll
    for (int o = 16; o; o >>= 1) s += __shfl_xor_sync(0xffffffffu, s, o);
    if ((c & 31) == 0) sh[c >> 5] = s;
    __syncthreads();
    float tot = 0.f;
    #pragma unroll
    for (int i = 0; i < 8; ++i) tot += sh[i];
    float mean = tot * (1.0f / CDIM);
    __syncthreads();
    float d = v - mean;
    float s2 = d * d;
    #pragma unroll
    for (int o = 16; o; o >>= 1) s2 += __shfl_xor_sync(0xffffffffu, s2, o);
    if ((c & 31) == 0) sh[c >> 5] = s2;
    __syncthreads();
    float v2 = 0.f;
    #pragma unroll
    for (int i = 0; i < 8; ++i) v2 += sh[i];
    float var = v2 * (1.0f / CDIM);
    float out = d * rsqrtf(var + 1e-5f) * g[c] + b[c];
    if (yf) yf[(size_t)tok * CDIM + c] = out;
    if (yb) yb[(size_t)tok * CDIM + c] = __float2bfloat16(out);
}

// ---------------- fp32 SGEMM (only for off/attn combined, N=216) -------------
#define BM 128
#define BN 64
#define BKK 16
__global__ __launch_bounds__(256)
void sgemm_kernel(const float* __restrict__ A, const float* __restrict__ Bw,
                  const float* __restrict__ bias, float* __restrict__ C,
                  int N, int Kd) {
    __shared__ float As[BKK][BM];
    __shared__ float Bs[BKK][BN];
    int t = threadIdx.x;
    int tx = t & 15;
    int ty = t >> 4;
    int m0 = blockIdx.y * BM;
    int n0 = blockIdx.x * BN;
    int ar = t >> 2;
    int ak = (t & 3) * 4;
    int brow = t >> 4;
    int bc4 = (t & 15) * 4;

    float acc[8][4];
    #pragma unroll
    for (int i = 0; i < 8; ++i)
        #pragma unroll
        for (int j = 0; j < 4; ++j) acc[i][j] = 0.f;

    for (int k0 = 0; k0 < Kd; k0 += BKK) {
        float4 a0 = *(const float4*)(A + (size_t)(m0 + ar) * Kd + k0 + ak);
        float4 a1 = *(const float4*)(A + (size_t)(m0 + ar + 64) * Kd + k0 + ak);
        float4 bv;
        const float* bp = Bw + (size_t)(k0 + brow) * N;
        if (n0 + bc4 + 4 <= N) {
            bv.x = bp[n0 + bc4 + 0]; bv.y = bp[n0 + bc4 + 1];
            bv.z = bp[n0 + bc4 + 2]; bv.w = bp[n0 + bc4 + 3];
        } else {
            bv.x = (n0 + bc4 + 0 < N) ? bp[n0 + bc4 + 0] : 0.f;
            bv.y = (n0 + bc4 + 1 < N) ? bp[n0 + bc4 + 1] : 0.f;
            bv.z = (n0 + bc4 + 2 < N) ? bp[n0 + bc4 + 2] : 0.f;
            bv.w = (n0 + bc4 + 3 < N) ? bp[n0 + bc4 + 3] : 0.f;
        }
        __syncthreads();
        As[ak + 0][ar] = a0.x; As[ak + 1][ar] = a0.y;
        As[ak + 2][ar] = a0.z; As[ak + 3][ar] = a0.w;
        As[ak + 0][ar + 64] = a1.x; As[ak + 1][ar + 64] = a1.y;
        As[ak + 2][ar + 64] = a1.z; As[ak + 3][ar + 64] = a1.w;
        Bs[brow][bc4 + 0] = bv.x; Bs[brow][bc4 + 1] = bv.y;
        Bs[brow][bc4 + 2] = bv.z; Bs[brow][bc4 + 3] = bv.w;
        __syncthreads();
        #pragma unroll
        for (int kk = 0; kk < BKK; ++kk) {
            float4 af0 = *(const float4*)&As[kk][ty * 8];
            float4 af1 = *(const float4*)&As[kk][ty * 8 + 4];
            float4 bf  = *(const float4*)&Bs[kk][tx * 4];
            float a[8] = {af0.x, af0.y, af0.z, af0.w, af1.x, af1.y, af1.z, af1.w};
            float bb[4] = {bf.x, bf.y, bf.z, bf.w};
            #pragma unroll
            for (int i = 0; i < 8; ++i)
                #pragma unroll
                for (int j = 0; j < 4; ++j)
                    acc[i][j] += a[i] * bb[j];
        }
    }
    #pragma unroll
    for (int i = 0; i < 8; ++i) {
        int row = m0 + ty * 8 + i;
        #pragma unroll
        for (int j = 0; j < 4; ++j) {
            int col = n0 + tx * 4 + j;
            if (col < N)
                C[(size_t)row * N + col] = acc[i][j] + bias[col];
        }
    }
}

// ---------------- bf16 tensor-core GEMM: 128x64x32 tile, mma.sync ------------
// EPI: 0 = bias -> bf16 out; 1 = bias+gelu -> bf16 out; 2 = bias+resid -> f32 out
#define HBM 128
#define HBN 64
#define HBK 32
#define ASTR 40   // elems per A smem row (80B, 16B-aligned, conflict-free)
#define BSTR 72   // elems per B smem row (144B, 16B-aligned, conflict-free)

template<int EPI>
__global__ __launch_bounds__(256)
void hgemm_kernel(const bf16* __restrict__ A, const bf16* __restrict__ B,
                  const float* __restrict__ bias, const float* __restrict__ resid,
                  void* __restrict__ Cp, int N, int K) {
    __shared__ bf16 As[2][HBM * ASTR];
    __shared__ bf16 Bs[2][HBK * BSTR];
    const int AbufB = HBM * ASTR * 2;
    const int BbufB = HBK * BSTR * 2;

    int t = threadIdx.x;
    int lane = t & 31, warp = t >> 5;
    int wm = (warp >> 1) * 32;   // warp row offset (4 warps along M)
    int wn = (warp & 1) * 32;    // warp col offset (2 warps along N)
    int m0 = blockIdx.y * HBM;
    int n0 = blockIdx.x * HBN;

    // ---- global load mapping ----
    int a_row = t >> 1;              // 0..127
    int a_col = (t & 1) * 16;        // elem offset (two 16B chunks per thread)
    int b_row = t >> 3;              // 0..31
    int b_col = (t & 7) * 8;         // elem offset
    const bf16* Ag = A + (size_t)(m0 + a_row) * K + a_col;
    const bf16* Bg = B + (size_t)b_row * N + n0 + b_col;
    uint32_t As_w = smem_u32(&As[0][0]) + (a_row * ASTR + a_col) * 2;
    uint32_t Bs_w = smem_u32(&Bs[0][0]) + (b_row * BSTR + b_col) * 2;

    // ---- ldmatrix lane offsets (bytes) ----
    uint32_t As_r = smem_u32(&As[0][0]);
    uint32_t Bs_r = smem_u32(&Bs[0][0]);
    uint32_t aoff[2], boff[2];
    #pragma unroll
    for (int mi = 0; mi < 2; ++mi)
        aoff[mi] = ((wm + mi * 16 + (lane & 15)) * ASTR + (lane >> 4) * 8) * 2;
    int tile = lane >> 3;
    #pragma unroll
    for (int ni = 0; ni < 2; ++ni)
        boff[ni] = (((tile & 1) * 8 + (lane & 7)) * BSTR + wn + ni * 16 + (tile >> 1) * 8) * 2;

    float acc[2][4][4];
    #pragma unroll
    for (int mi = 0; mi < 2; ++mi)
        #pragma unroll
        for (int nj = 0; nj < 4; ++nj)
            #pragma unroll
            for (int r = 0; r < 4; ++r) acc[mi][nj][r] = 0.f;

    int niter = K / HBK;

    // prefetch iter 0 into buf 0
    {
        asm volatile("cp.async.cg.shared.global [%0], [%1], 16;\n" :: "r"(As_w), "l"(Ag));
        asm volatile("cp.async.cg.shared.global [%0], [%1], 16;\n" :: "r"(As_w + 16), "l"(Ag + 8));
        asm volatile("cp.async.cg.shared.global [%0], [%1], 16;\n" :: "r"(Bs_w), "l"(Bg));
        asm volatile("cp.async.commit_group;\n");
    }

    for (int it = 0; it < niter; ++it) {
        if (it + 1 < niter) {
            int buf = (it + 1) & 1;
            const bf16* ag = Ag + (it + 1) * HBK;
            const bf16* bg = Bg + (size_t)(it + 1) * HBK * N;
            asm volatile("cp.async.cg.shared.global [%0], [%1], 16;\n" :: "r"(As_w + buf * AbufB), "l"(ag));
            asm volatile("cp.async.cg.shared.global [%0], [%1], 16;\n" :: "r"(As_w + buf * AbufB + 16), "l"(ag + 8));
            asm volatile("cp.async.cg.shared.global [%0], [%1], 16;\n" :: "r"(Bs_w + buf * BbufB), "l"(bg));
            asm volatile("cp.async.commit_group;\n");
            asm volatile("cp.async.wait_group 1;\n");
        } else {
            asm volatile("cp.async.wait_group 0;\n");
        }
        __syncthreads();

        int buf = it & 1;
        uint32_t Ab = As_r + buf * AbufB;
        uint32_t Bb = Bs_r + buf * BbufB;

        #pragma unroll
        for (int kk = 0; kk < 2; ++kk) {   // two k16 steps
            uint32_t a[2][4];
            #pragma unroll
            for (int mi = 0; mi < 2; ++mi) {
                uint32_t addr = Ab + aoff[mi] + kk * 32;   // kk*16 elems * 2B
                asm volatile("ldmatrix.sync.aligned.m8n8.x4.shared.b16 {%0,%1,%2,%3}, [%4];"
                    : "=r"(a[mi][0]), "=r"(a[mi][1]), "=r"(a[mi][2]), "=r"(a[mi][3]) : "r"(addr));
            }
            uint32_t bf[2][4];
            #pragma unroll
            for (int ni = 0; ni < 2; ++ni) {
                uint32_t addr = Bb + boff[ni] + kk * 16 * BSTR * 2;
                asm volatile("ldmatrix.sync.aligned.m8n8.x4.trans.shared.b16 {%0,%1,%2,%3}, [%4];"
                    : "=r"(bf[ni][0]), "=r"(bf[ni][1]), "=r"(bf[ni][2]), "=r"(bf[ni][3]) : "r"(addr));
            }
            #pragma unroll
            for (int mi = 0; mi < 2; ++mi)
                #pragma unroll
                for (int nj = 0; nj < 4; ++nj) {
                    uint32_t b0 = bf[nj >> 1][(nj & 1) * 2];
                    uint32_t b1 = bf[nj >> 1][(nj & 1) * 2 + 1];
                    asm volatile(
                        "mma.sync.aligned.m16n8k16.row.col.f32.bf16.bf16.f32 "
                        "{%0,%1,%2,%3}, {%4,%5,%6,%7}, {%8,%9}, {%0,%1,%2,%3};"
                        : "+f"(acc[mi][nj][0]), "+f"(acc[mi][nj][1]),
                          "+f"(acc[mi][nj][2]), "+f"(acc[mi][nj][3])
                        : "r"(a[mi][0]), "r"(a[mi][1]), "r"(a[mi][2]), "r"(a[mi][3]),
                          "r"(b0), "r"(b1));
                }
        }
        __syncthreads();
    }

    // ---- epilogue ----
    int r_base = m0 + wm + (lane >> 2);
    int c_base = n0 + wn + (lane & 3) * 2;
    #pragma unroll
    for (int mi = 0; mi < 2; ++mi) {
        #pragma unroll
        for (int nj = 0; nj < 4; ++nj) {
            int r = r_base + mi * 16;
            int c = c_base + nj * 8;
            float bx = bias[c], by = bias[c + 1];
            float o00 = acc[mi][nj][0] + bx;
            float o01 = acc[mi][nj][1] + by;
            float o10 = acc[mi][nj][2] + bx;
            float o11 = acc[mi][nj][3] + by;
            if (EPI == 1) {
                o00 = gelu_f(o00); o01 = gelu_f(o01);
                o10 = gelu_f(o10); o11 = gelu_f(o11);
            }
            if (EPI == 2) {
                const float* rp0 = resid + (size_t)r * N + c;
                const float* rp1 = resid + (size_t)(r + 8) * N + c;
                float* Cf = (float*)Cp;
                float2 v0 = {o00 + rp0[0], o01 + rp0[1]};
                float2 v1 = {o10 + rp1[0], o11 + rp1[1]};
                *(float2*)(Cf + (size_t)r * N + c) = v0;
                *(float2*)(Cf + (size_t)(r + 8) * N + c) = v1;
            } else {
                bf16* Cb = (bf16*)Cp;
                __nv_bfloat162 v0 = {__float2bfloat16(o00), __float2bfloat16(o01)};
                __nv_bfloat162 v1 = {__float2bfloat16(o10), __float2bfloat16(o11)};
                *(__nv_bfloat162*)(Cb + (size_t)r * N + c) = v0;
                *(__nv_bfloat162*)(Cb + (size_t)(r + 8) * N + c) = v1;
            }
        }
    }
}

// ---------------- Deformable sampling + softmax + aggregation ----------------
__global__ void sample_kernel(const bf16* __restrict__ v, const float* __restrict__ offattn,
                              const float* __restrict__ rp, bf16* __restrict__ agg) {
    int gw = blockIdx.x * 8 + (threadIdx.x >> 5);
    int lane = threadIdx.x & 31;
    int head = gw & 7;
    int tg = gw >> 3;
    int bb = tg >> 13;
    int pos = tg & 8191;

    const float* lg = offattn + (size_t)tg * 216 + 144 + head * 9;
    float w[9];
    float mx = -1e30f;
    #pragma unroll
    for (int k = 0; k < 9; ++k) { w[k] = lg[k]; mx = fmaxf(mx, w[k]); }
    float sum = 0.f;
    #pragma unroll
    for (int k = 0; k < 9; ++k) { w[k] = expf(w[k] - mx); sum += w[k]; }
    float inv = 1.0f / sum;

    const float* rpp  = rp + (size_t)pos * 18;
    const float* offp = offattn + (size_t)tg * 216 + head * 18;
    const bf16* vc = v + head * 32 + lane;
    int base = bb << 13;
    float acc = 0.f;
    #pragma unroll
    for (int k = 0; k < 9; ++k) {
        float cx = (rpp[k * 2 + 0] + offp[k * 2 + 0] + 1.0f) * 0.5f * 127.0f;
        float cy = (rpp[k * 2 + 1] + offp[k * 2 + 1] + 1.0f) * 0.5f * 63.0f;
        float fx = floorf(cx), fy = floorf(cy);
        float wx = cx - fx, wy = cy - fy;
        int x0 = min(max((int)fx, 0), 127);
        int x1 = min(max((int)fx + 1, 0), 127);
        int y0 = min(max((int)fy, 0), 63);
        int y1 = min(max((int)fy + 1, 0), 63);
        float v00 = __bfloat162float(vc[(size_t)(base + y0 * 128 + x0) * 256]);
        float v01 = __bfloat162float(vc[(size_t)(base + y0 * 128 + x1) * 256]);
        float v10 = __bfloat162float(vc[(size_t)(base + y1 * 128 + x0) * 256]);
        float v11 = __bfloat162float(vc[(size_t)(base + y1 * 128 + x1) * 256]);
        float s = v00 * (1.f - wy) * (1.f - wx) + v01 * (1.f - wy) * wx
                + v10 * wy * (1.f - wx) + v11 * wy * wx;
        acc += s * (w[k] * inv);
    }
    agg[(size_t)tg * 256 + head * 32 + lane] = __float2bfloat16(acc);
}

// ---------------- Depthwise 3x3 conv (circular W, zero H) + bias + GELU ------
// 2 channels per thread via bf16x2 (full 128B/warp coalescing)
__global__ void dwconv_kernel(const bf16* __restrict__ h, const float* __restrict__ wdw,
                              const float* __restrict__ bdw, bf16* __restrict__ o) {
    int c2 = blockIdx.x * 256 + threadIdx.x;   // 0..511 (channel pair)
    int tok = blockIdx.y;
    int bb = tok >> 13;
    int y = (tok >> 7) & 63;
    int x = tok & 127;
    int c = c2 * 2;
    float acc0 = bdw[c], acc1 = bdw[c + 1];
    const __nv_bfloat162* h2p = (const __nv_bfloat162*)h;
    #pragma unroll
    for (int dy = -1; dy <= 1; ++dy) {
        int yy = y + dy;
        if (yy < 0 || yy > 63) continue;
        int rowbase = (bb << 13) + (yy << 7);
        #pragma unroll
        for (int dx = -1; dx <= 1; ++dx) {
            int xx = (x + dx + 128) & 127;
            __nv_bfloat162 hv = h2p[(size_t)(rowbase + xx) * (HID / 2) + c2];
            float w0 = wdw[c * 9 + (dy + 1) * 3 + (dx + 1)];
            float w1 = wdw[(c + 1) * 9 + (dy + 1) * 3 + (dx + 1)];
            acc0 += __bfloat162float(hv.x) * w0;
            acc1 += __bfloat162float(hv.y) * w1;
        }
    }
    __nv_bfloat162 ov = {__float2bfloat16(gelu_f(acc0)), __float2bfloat16(gelu_f(acc1))};
    *(__nv_bfloat162*)(o + (size_t)tok * HID + c) = ov;
}

// ---------------- launch ----------------
extern "C" void kernel_launch(void* const* d_in, const int* in_sizes, int n_in,
                              void* d_out, int out_size) {
    const float* x      = (const float*)d_in[0];
    const float* rp     = (const float*)d_in[1];
    const float* ln1_g  = (const float*)d_in[2];
    const float* ln1_b  = (const float*)d_in[3];
    const float* w_v    = (const float*)d_in[4];
    const float* b_v    = (const float*)d_in[5];
    const float* w_off  = (const float*)d_in[6];
    const float* b_off  = (const float*)d_in[7];
    const float* w_attn = (const float*)d_in[8];
    const float* b_attn = (const float*)d_in[9];
    const float* w_out  = (const float*)d_in[10];
    const float* b_out  = (const float*)d_in[11];
    const float* ln2_g  = (const float*)d_in[12];
    const float* ln2_b  = (const float*)d_in[13];
    const float* w1     = (const float*)d_in[14];
    const float* b1     = (const float*)d_in[15];
    const float* w_dw   = (const float*)d_in[16];
    const float* b_dw   = (const float*)d_in[17];
    const float* w2     = (const float*)d_in[18];
    const float* b2     = (const float*)d_in[19];
    float* out = (float*)d_out;

    float *xn, *offattn, *xres, *wcat, *bcat;
    bf16 *xnb, *vb, *aggb, *yb, *hb, *h2b, *wvb, *woutb, *w1b, *w2b;
    cudaGetSymbolAddress((void**)&xn,      g_xn);
    cudaGetSymbolAddress((void**)&offattn, g_offattn);
    cudaGetSymbolAddress((void**)&xres,    g_xres);
    cudaGetSymbolAddress((void**)&wcat,    g_wcat);
    cudaGetSymbolAddress((void**)&bcat,    g_bcat);
    cudaGetSymbolAddress((void**)&xnb,     g_xnb);
    cudaGetSymbolAddress((void**)&vb,      g_vb);
    cudaGetSymbolAddress((void**)&aggb,    g_aggb);
    cudaGetSymbolAddress((void**)&yb,      g_yb);
    cudaGetSymbolAddress((void**)&hb,      g_hb);
    cudaGetSymbolAddress((void**)&h2b,     g_h2b);
    cudaGetSymbolAddress((void**)&wvb,     g_wvb);
    cudaGetSymbolAddress((void**)&woutb,   g_woutb);
    cudaGetSymbolAddress((void**)&w1b,     g_w1b);
    cudaGetSymbolAddress((void**)&w2b,     g_w2b);

    // weight prep
    f2bf_all_kernel<<<(655360 + 255) / 256, 256>>>(w_v, w_out, w1, w2, wvb, woutb, w1b, w2b);
    wcat_kernel<<<(256 * 216 + 255) / 256, 256>>>(w_off, w_attn, b_off, b_attn, wcat, bcat);

    // 1. LN1 -> xn (f32) + xnb (bf16)
    ln_kernel<<<NTOK, 256>>>(x, ln1_g, ln1_b, xn, xnb);
    // 2. v projection (bf16 TC)
    hgemm_kernel<0><<<dim3(256 / HBN, NTOK / HBM), 256>>>(xnb, wvb, b_v, nullptr, vb, 256, 256);
    // 3. offsets+attn combined (fp32)
    sgemm_kernel<<<dim3((216 + BN - 1) / BN, NTOK / BM), 256>>>(xn, wcat, bcat, offattn, 216, 256);
    // 4. softmax + bilinear sampling + aggregation
    sample_kernel<<<NTOK, 256>>>(vb, offattn, rp, aggb);
    // 5. output proj + residual -> xres (f32)
    hgemm_kernel<2><<<dim3(256 / HBN, NTOK / HBM), 256>>>(aggb, woutb, b_out, x, xres, 256, 256);
    // 6. LN2 -> yb (bf16)
    ln_kernel<<<NTOK, 256>>>(xres, ln2_g, ln2_b, nullptr, yb);
    // 7. fc1 + GELU (bf16 TC)
    hgemm_kernel<1><<<dim3(HID / HBN, NTOK / HBM), 256>>>(yb, w1b, b1, nullptr, hb, HID, 256);
    // 8. depthwise conv + GELU
    dwconv_kernel<<<dim3(HID / 512, NTOK), 256>>>(hb, w_dw, b_dw, h2b);
    // 9. fc2 + residual -> out (f32)
    hgemm_kernel<2><<<dim3(256 / HBN, NTOK / HBM), 256>>>(h2b, w2b, b2, xres, out, 256, 1024);
}

// round 4
// speedup vs baseline: 2.1967x; 1.0533x over previous
#include <cuda_runtime.h>
#include <cuda_bf16.h>
#include <math.h>
#include <stdint.h>

typedef __nv_bfloat16 bf16;

#define NTOK 16384
#define CDIM 256
#define HID  1024

// -------- scratch (__device__ globals; no allocations allowed) --------
__device__ float g_xn     [NTOK * CDIM];
__device__ float g_offattn[NTOK * 216];
__device__ float g_xres   [NTOK * CDIM];
__device__ bf16  g_xnb    [NTOK * CDIM];
__device__ bf16  g_vb     [NTOK * CDIM];
__device__ bf16  g_aggb   [NTOK * CDIM];
__device__ bf16  g_yb     [NTOK * CDIM];
__device__ bf16  g_hb     [NTOK * HID];
__device__ bf16  g_h2b    [NTOK * HID];
__device__ bf16  g_wvb    [256 * 256];
__device__ bf16  g_woutb  [256 * 256];
__device__ bf16  g_w1b    [256 * 1024];
__device__ bf16  g_w2b    [1024 * 256];
__device__ float g_wcat   [256 * 216];
__device__ float g_bcat   [216];

__device__ __forceinline__ float gelu_f(float v) {
    return 0.5f * v * (1.0f + erff(v * 0.7071067811865476f));
}

__device__ __forceinline__ uint32_t smem_u32(const void* p) {
    uint32_t a;
    asm("{ .reg .u64 t; cvta.to.shared.u64 t, %1; cvt.u32.u64 %0, t; }" : "=r"(a) : "l"(p));
    return a;
}

// ---------------- weight conversions ----------------
__global__ void f2bf_all_kernel(const float* wv, const float* wout, const float* w1,
                                const float* w2, bf16* wvb, bf16* woutb, bf16* w1b, bf16* w2b) {
    int i = blockIdx.x * 256 + threadIdx.x;
    if (i < 65536) { wvb[i] = __float2bfloat16(wv[i]); return; }
    i -= 65536;
    if (i < 65536) { woutb[i] = __float2bfloat16(wout[i]); return; }
    i -= 65536;
    if (i < 262144) { w1b[i] = __float2bfloat16(w1[i]); return; }
    i -= 262144;
    if (i < 262144) { w2b[i] = __float2bfloat16(w2[i]); return; }
}

__global__ void wcat_kernel(const float* w_off, const float* w_attn,
                            const float* b_off, const float* b_attn,
                            float* wcat, float* bcat) {
    int i = blockIdx.x * 256 + threadIdx.x;
    if (i < 256 * 216) {
        int k = i / 216, j = i % 216;
        wcat[i] = (j < 144) ? w_off[k * 144 + j] : w_attn[k * 72 + (j - 144)];
    }
    if (i < 216) bcat[i] = (i < 144) ? b_off[i] : b_attn[i - 144];
}

// ---------------- LayerNorm: one block per token, dual output ----------------
__global__ void ln_kernel(const float* __restrict__ x, const float* __restrict__ g,
                          const float* __restrict__ b, float* __restrict__ yf,
                          bf16* __restrict__ yb) {
    int tok = blockIdx.x;
    int c = threadIdx.x;
    float v = x[(size_t)tok * CDIM + c];
    __shared__ float sh[8];
    float s = v;
    #pragma unroll
    for (int o = 16; o; o >>= 1) s += __shfl_xor_sync(0xffffffffu, s, o);
    if ((c & 31) == 0) sh[c >> 5] = s;
    __syncthreads();
    float tot = 0.f;
    #pragma unroll
    for (int i = 0; i < 8; ++i) tot += sh[i];
    float mean = tot * (1.0f / CDIM);
    __syncthreads();
    float d = v - mean;
    float s2 = d * d;
    #pragma unroll
    for (int o = 16; o; o >>= 1) s2 += __shfl_xor_sync(0xffffffffu, s2, o);
    if ((c & 31) == 0) sh[c >> 5] = s2;
    __syncthreads();
    float v2 = 0.f;
    #pragma unroll
    for (int i = 0; i < 8; ++i) v2 += sh[i];
    float var = v2 * (1.0f / CDIM);
    float out = d * rsqrtf(var + 1e-5f) * g[c] + b[c];
    if (yf) yf[(size_t)tok * CDIM + c] = out;
    if (yb) yb[(size_t)tok * CDIM + c] = __float2bfloat16(out);
}

// ---------------- fp32 SGEMM (off/attn combined, N=216) ----------------------
#define BM 128
#define BN 64
#define BKK 16
__global__ __launch_bounds__(256)
void sgemm_kernel(const float* __restrict__ A, const float* __restrict__ Bw,
                  const float* __restrict__ bias, float* __restrict__ C,
                  int N, int Kd) {
    __shared__ float As[BKK][BM];
    __shared__ float Bs[BKK][BN];
    int t = threadIdx.x;
    int tx = t & 15;
    int ty = t >> 4;
    int m0 = blockIdx.y * BM;
    int n0 = blockIdx.x * BN;
    int ar = t >> 2;
    int ak = (t & 3) * 4;
    int brow = t >> 4;
    int bc4 = (t & 15) * 4;

    float acc[8][4];
    #pragma unroll
    for (int i = 0; i < 8; ++i)
        #pragma unroll
        for (int j = 0; j < 4; ++j) acc[i][j] = 0.f;

    for (int k0 = 0; k0 < Kd; k0 += BKK) {
        float4 a0 = *(const float4*)(A + (size_t)(m0 + ar) * Kd + k0 + ak);
        float4 a1 = *(const float4*)(A + (size_t)(m0 + ar + 64) * Kd + k0 + ak);
        float4 bv;
        const float* bp = Bw + (size_t)(k0 + brow) * N;
        if (n0 + bc4 + 4 <= N) {
            bv.x = bp[n0 + bc4 + 0]; bv.y = bp[n0 + bc4 + 1];
            bv.z = bp[n0 + bc4 + 2]; bv.w = bp[n0 + bc4 + 3];
        } else {
            bv.x = (n0 + bc4 + 0 < N) ? bp[n0 + bc4 + 0] : 0.f;
            bv.y = (n0 + bc4 + 1 < N) ? bp[n0 + bc4 + 1] : 0.f;
            bv.z = (n0 + bc4 + 2 < N) ? bp[n0 + bc4 + 2] : 0.f;
            bv.w = (n0 + bc4 + 3 < N) ? bp[n0 + bc4 + 3] : 0.f;
        }
        __syncthreads();
        As[ak + 0][ar] = a0.x; As[ak + 1][ar] = a0.y;
        As[ak + 2][ar] = a0.z; As[ak + 3][ar] = a0.w;
        As[ak + 0][ar + 64] = a1.x; As[ak + 1][ar + 64] = a1.y;
        As[ak + 2][ar + 64] = a1.z; As[ak + 3][ar + 64] = a1.w;
        Bs[brow][bc4 + 0] = bv.x; Bs[brow][bc4 + 1] = bv.y;
        Bs[brow][bc4 + 2] = bv.z; Bs[brow][bc4 + 3] = bv.w;
        __syncthreads();
        #pragma unroll
        for (int kk = 0; kk < BKK; ++kk) {
            float4 af0 = *(const float4*)&As[kk][ty * 8];
            float4 af1 = *(const float4*)&As[kk][ty * 8 + 4];
            float4 bf  = *(const float4*)&Bs[kk][tx * 4];
            float a[8] = {af0.x, af0.y, af0.z, af0.w, af1.x, af1.y, af1.z, af1.w};
            float bb[4] = {bf.x, bf.y, bf.z, bf.w};
            #pragma unroll
            for (int i = 0; i < 8; ++i)
                #pragma unroll
                for (int j = 0; j < 4; ++j)
                    acc[i][j] += a[i] * bb[j];
        }
    }
    #pragma unroll
    for (int i = 0; i < 8; ++i) {
        int row = m0 + ty * 8 + i;
        #pragma unroll
        for (int j = 0; j < 4; ++j) {
            int col = n0 + tx * 4 + j;
            if (col < N)
                C[(size_t)row * N + col] = acc[i][j] + bias[col];
        }
    }
}

// ---------------- bf16 mma.sync GEMM: 128x128x32 tile, 3-stage pipeline ------
// A [M,K] bf16; B [K,N] bf16. 8 warps as 4(M) x 2(N); warp tile 32x64.
// EPI: 0 = bias -> bf16; 1 = bias+gelu -> bf16; 2 = bias+resid -> f32
#define PBM 128
#define PBN 128
#define PBK 32
#define PASTR 80                 // bytes per A smem row (40 elems, padded)
#define PBSTR 272                // bytes per B smem row (136 elems, padded)
#define PA_ST (PBM * PASTR)      // 10240
#define PB_ST (PBK * PBSTR)      // 8704
#define PSTG  (PA_ST + PB_ST)    // 18944
#define PSMEM (3 * PSTG)         // 56832

template<int EPI>
__global__ __launch_bounds__(256)
void hgemm_kernel(const bf16* __restrict__ A, const bf16* __restrict__ B,
                  const float* __restrict__ bias, const float* __restrict__ resid,
                  void* __restrict__ Cp, int N, int K) {
    extern __shared__ char sm_[];
    uint32_t S0 = smem_u32(sm_);

    int t = threadIdx.x;
    int lane = t & 31, warp = t >> 5;
    int wm = (warp & 3) * 32;    // 4 warps along M
    int wn = (warp >> 2) * 64;   // 2 warps along N
    int m0 = blockIdx.y * PBM;
    int n0 = blockIdx.x * PBN;

    // ---- global->smem mapping ----
    int a_row = t >> 1;                 // 0..127
    int a_c16 = (t & 1) * 2;            // 16B-chunk index (of 4 per row)
    const bf16* Ag = A + (size_t)(m0 + a_row) * K + a_c16 * 8;
    uint32_t a_s = S0 + a_row * PASTR + a_c16 * 16;
    int b_row = t >> 3;                 // 0..31
    int b_c16 = (t & 7) * 2;            // of 16 per row
    const bf16* Bg = B + (size_t)b_row * N + n0 + b_c16 * 8;
    uint32_t b_s = S0 + PA_ST + b_row * PBSTR + b_c16 * 16;

    auto prefetch = [&](int chunk) {
        int st = chunk % 3;
        const bf16* ag = Ag + chunk * PBK;
        const bf16* bg = Bg + (size_t)chunk * PBK * N;
        uint32_t sa = a_s + st * PSTG;
        uint32_t sb = b_s + st * PSTG;
        asm volatile("cp.async.cg.shared.global [%0], [%1], 16;" :: "r"(sa), "l"(ag));
        asm volatile("cp.async.cg.shared.global [%0], [%1], 16;" :: "r"(sa + 16), "l"(ag + 8));
        asm volatile("cp.async.cg.shared.global [%0], [%1], 16;" :: "r"(sb), "l"(bg));
        asm volatile("cp.async.cg.shared.global [%0], [%1], 16;" :: "r"(sb + 16), "l"(bg + 8));
        asm volatile("cp.async.commit_group;");
    };

    // ---- ldmatrix lane offsets (bytes, within stage) ----
    uint32_t aoff[2], boff[4];
    #pragma unroll
    for (int mi = 0; mi < 2; ++mi)
        aoff[mi] = (wm + mi * 16 + (lane & 15)) * PASTR + (lane >> 4) * 16;
    int tile = lane >> 3;
    #pragma unroll
    for (int ni = 0; ni < 4; ++ni)
        boff[ni] = PA_ST + ((tile & 1) * 8 + (lane & 7)) * PBSTR
                 + (wn + ni * 16 + (tile >> 1) * 8) * 2;

    float acc[2][8][4];
    #pragma unroll
    for (int mi = 0; mi < 2; ++mi)
        #pragma unroll
        for (int nj = 0; nj < 8; ++nj)
            #pragma unroll
            for (int r = 0; r < 4; ++r) acc[mi][nj][r] = 0.f;

    int niter = K / PBK;
    prefetch(0);
    prefetch(1);

    for (int it = 0; it < niter; ++it) {
        if (it + 1 < niter) asm volatile("cp.async.wait_group 1;");
        else                asm volatile("cp.async.wait_group 0;");
        __syncthreads();

        uint32_t Sb = S0 + (it % 3) * PSTG;
        #pragma unroll
        for (int kk = 0; kk < 2; ++kk) {
            uint32_t a[2][4];
            #pragma unroll
            for (int mi = 0; mi < 2; ++mi) {
                uint32_t addr = Sb + aoff[mi] + kk * 32;
                asm volatile("ldmatrix.sync.aligned.m8n8.x4.shared.b16 {%0,%1,%2,%3}, [%4];"
                    : "=r"(a[mi][0]), "=r"(a[mi][1]), "=r"(a[mi][2]), "=r"(a[mi][3]) : "r"(addr));
            }
            uint32_t bq[4][4];
            #pragma unroll
            for (int ni = 0; ni < 4; ++ni) {
                uint32_t addr = Sb + boff[ni] + kk * 16 * PBSTR;
                asm volatile("ldmatrix.sync.aligned.m8n8.x4.trans.shared.b16 {%0,%1,%2,%3}, [%4];"
                    : "=r"(bq[ni][0]), "=r"(bq[ni][1]), "=r"(bq[ni][2]), "=r"(bq[ni][3]) : "r"(addr));
            }
            #pragma unroll
            for (int mi = 0; mi < 2; ++mi)
                #pragma unroll
                for (int nj = 0; nj < 8; ++nj) {
                    uint32_t b0 = bq[nj >> 1][(nj & 1) * 2];
                    uint32_t b1 = bq[nj >> 1][(nj & 1) * 2 + 1];
                    asm volatile(
                        "mma.sync.aligned.m16n8k16.row.col.f32.bf16.bf16.f32 "
                        "{%0,%1,%2,%3}, {%4,%5,%6,%7}, {%8,%9}, {%0,%1,%2,%3};"
                        : "+f"(acc[mi][nj][0]), "+f"(acc[mi][nj][1]),
                          "+f"(acc[mi][nj][2]), "+f"(acc[mi][nj][3])
                        : "r"(a[mi][0]), "r"(a[mi][1]), "r"(a[mi][2]), "r"(a[mi][3]),
                          "r"(b0), "r"(b1));
                }
        }
        __syncthreads();
        if (it + 2 < niter) prefetch(it + 2);
    }

    // ---- epilogue ----
    int r_base = m0 + wm + (lane >> 2);
    int c_base = n0 + wn + (lane & 3) * 2;
    #pragma unroll
    for (int mi = 0; mi < 2; ++mi) {
        #pragma unroll
        for (int nj = 0; nj < 8; ++nj) {
            int r = r_base + mi * 16;
            int c = c_base + nj * 8;
            float bx = bias[c], by = bias[c + 1];
            float o00 = acc[mi][nj][0] + bx;
            float o01 = acc[mi][nj][1] + by;
            float o10 = acc[mi][nj][2] + bx;
            float o11 = acc[mi][nj][3] + by;
            if (EPI == 1) {
                o00 = gelu_f(o00); o01 = gelu_f(o01);
                o10 = gelu_f(o10); o11 = gelu_f(o11);
            }
            if (EPI == 2) {
                const float* rp0 = resid + (size_t)r * N + c;
                const float* rp1 = resid + (size_t)(r + 8) * N + c;
                float* Cf = (float*)Cp;
                float2 v0 = {o00 + rp0[0], o01 + rp0[1]};
                float2 v1 = {o10 + rp1[0], o11 + rp1[1]};
                *(float2*)(Cf + (size_t)r * N + c) = v0;
                *(float2*)(Cf + (size_t)(r + 8) * N + c) = v1;
            } else {
                bf16* Cb = (bf16*)Cp;
                __nv_bfloat162 v0 = {__float2bfloat16(o00), __float2bfloat16(o01)};
                __nv_bfloat162 v1 = {__float2bfloat16(o10), __float2bfloat16(o11)};
                *(__nv_bfloat162*)(Cb + (size_t)r * N + c) = v0;
                *(__nv_bfloat162*)(Cb + (size_t)(r + 8) * N + c) = v1;
            }
        }
    }
}

// ---------------- Deformable sampling + softmax + aggregation ----------------
__global__ void sample_kernel(const bf16* __restrict__ v, const float* __restrict__ offattn,
                              const float* __restrict__ rp, bf16* __restrict__ agg) {
    int gw = blockIdx.x * 8 + (threadIdx.x >> 5);
    int lane = threadIdx.x & 31;
    int head = gw & 7;
    int tg = gw >> 3;
    int bb = tg >> 13;
    int pos = tg & 8191;

    const float* lg = offattn + (size_t)tg * 216 + 144 + head * 9;
    float w[9];
    float mx = -1e30f;
    #pragma unroll
    for (int k = 0; k < 9; ++k) { w[k] = lg[k]; mx = fmaxf(mx, w[k]); }
    float sum = 0.f;
    #pragma unroll
    for (int k = 0; k < 9; ++k) { w[k] = expf(w[k] - mx); sum += w[k]; }
    float inv = 1.0f / sum;

    const float* rpp  = rp + (size_t)pos * 18;
    const float* offp = offattn + (size_t)tg * 216 + head * 18;
    const bf16* vc = v + head * 32 + lane;
    int base = bb << 13;
    float acc = 0.f;
    #pragma unroll
    for (int k = 0; k < 9; ++k) {
        float cx = (rpp[k * 2 + 0] + offp[k * 2 + 0] + 1.0f) * 0.5f * 127.0f;
        float cy = (rpp[k * 2 + 1] + offp[k * 2 + 1] + 1.0f) * 0.5f * 63.0f;
        float fx = floorf(cx), fy = floorf(cy);
        float wx = cx - fx, wy = cy - fy;
        int x0 = min(max((int)fx, 0), 127);
        int x1 = min(max((int)fx + 1, 0), 127);
        int y0 = min(max((int)fy, 0), 63);
        int y1 = min(max((int)fy + 1, 0), 63);
        float v00 = __bfloat162float(vc[(size_t)(base + y0 * 128 + x0) * 256]);
        float v01 = __bfloat162float(vc[(size_t)(base + y0 * 128 + x1) * 256]);
        float v10 = __bfloat162float(vc[(size_t)(base + y1 * 128 + x0) * 256]);
        float v11 = __bfloat162float(vc[(size_t)(base + y1 * 128 + x1) * 256]);
        float s = v00 * (1.f - wy) * (1.f - wx) + v01 * (1.f - wy) * wx
                + v10 * wy * (1.f - wx) + v11 * wy * wx;
        acc += s * (w[k] * inv);
    }
    agg[(size_t)tg * 256 + head * 32 + lane] = __float2bfloat16(acc);
}

// ---------------- Depthwise 3x3 conv: sliding window along width -------------
// Thread owns (channel-pair, y, batch) and iterates x; 3 loads per output.
__global__ void dwconv_kernel(const bf16* __restrict__ h, const float* __restrict__ wdw,
                              const float* __restrict__ bdw, bf16* __restrict__ o) {
    int c2 = blockIdx.x * 256 + threadIdx.x;   // 0..511
    int y = blockIdx.y;                         // 0..63
    int bb = blockIdx.z;                        // 0..1
    int c = c2 * 2;

    float w0[9], w1[9];
    #pragma unroll
    for (int i = 0; i < 9; ++i) { w0[i] = wdw[c * 9 + i]; w1[i] = wdw[(c + 1) * 9 + i]; }
    float bb0 = bdw[c], bb1 = bdw[c + 1];

    const __nv_bfloat162* hp = (const __nv_bfloat162*)h;
    size_t base = ((size_t)(bb << 13) + y * 128) * 512 + c2;
    bool hu = (y > 0), hd = (y < 63);
    __nv_bfloat162 zero = __float2bfloat162_rn(0.f);

    __nv_bfloat162 cm[3], cc[3], cn[3];
    {
        size_t p = base + 127 * 512;
        cm[0] = hu ? hp[p - 65536] : zero; cm[1] = hp[p]; cm[2] = hd ? hp[p + 65536] : zero;
        p = base;
        cc[0] = hu ? hp[p - 65536] : zero; cc[1] = hp[p]; cc[2] = hd ? hp[p + 65536] : zero;
    }
    bf16* op = o + ((size_t)(bb << 13) + y * 128) * 1024 + c;

    for (int x = 0; x < 128; ++x) {
        size_t p = base + ((x + 1) & 127) * 512;
        cn[0] = hu ? hp[p - 65536] : zero; cn[1] = hp[p]; cn[2] = hd ? hp[p + 65536] : zero;

        float a0 = bb0, a1 = bb1;
        #pragma unroll
        for (int dy = 0; dy < 3; ++dy) {
            float2 vm = __bfloat1622float2(cm[dy]);
            float2 vc = __bfloat1622float2(cc[dy]);
            float2 vp = __bfloat1622float2(cn[dy]);
            a0 += vm.x * w0[dy * 3 + 0] + vc.x * w0[dy * 3 + 1] + vp.x * w0[dy * 3 + 2];
            a1 += vm.y * w1[dy * 3 + 0] + vc.y * w1[dy * 3 + 1] + vp.y * w1[dy * 3 + 2];
        }
        __nv_bfloat162 ov = {__float2bfloat16(gelu_f(a0)), __float2bfloat16(gelu_f(a1))};
        *(__nv_bfloat162*)(op + (size_t)x * 1024) = ov;

        #pragma unroll
        for (int i = 0; i < 3; ++i) { cm[i] = cc[i]; cc[i] = cn[i]; }
    }
}

// ---------------- launch ----------------
extern "C" void kernel_launch(void* const* d_in, const int* in_sizes, int n_in,
                              void* d_out, int out_size) {
    const float* x      = (const float*)d_in[0];
    const float* rp     = (const float*)d_in[1];
    const float* ln1_g  = (const float*)d_in[2];
    const float* ln1_b  = (const float*)d_in[3];
    const float* w_v    = (const float*)d_in[4];
    const float* b_v    = (const float*)d_in[5];
    const float* w_off  = (const float*)d_in[6];
    const float* b_off  = (const float*)d_in[7];
    const float* w_attn = (const float*)d_in[8];
    const float* b_attn = (const float*)d_in[9];
    const float* w_out  = (const float*)d_in[10];
    const float* b_out  = (const float*)d_in[11];
    const float* ln2_g  = (const float*)d_in[12];
    const float* ln2_b  = (const float*)d_in[13];
    const float* w1     = (const float*)d_in[14];
    const float* b1     = (const float*)d_in[15];
    const float* w_dw   = (const float*)d_in[16];
    const float* b_dw   = (const float*)d_in[17];
    const float* w2     = (const float*)d_in[18];
    const float* b2     = (const float*)d_in[19];
    float* out = (float*)d_out;

    float *xn, *offattn, *xres, *wcat, *bcat;
    bf16 *xnb, *vb, *aggb, *yb, *hb, *h2b, *wvb, *woutb, *w1b, *w2b;
    cudaGetSymbolAddress((void**)&xn,      g_xn);
    cudaGetSymbolAddress((void**)&offattn, g_offattn);
    cudaGetSymbolAddress((void**)&xres,    g_xres);
    cudaGetSymbolAddress((void**)&wcat,    g_wcat);
    cudaGetSymbolAddress((void**)&bcat,    g_bcat);
    cudaGetSymbolAddress((void**)&xnb,     g_xnb);
    cudaGetSymbolAddress((void**)&vb,      g_vb);
    cudaGetSymbolAddress((void**)&aggb,    g_aggb);
    cudaGetSymbolAddress((void**)&yb,      g_yb);
    cudaGetSymbolAddress((void**)&hb,      g_hb);
    cudaGetSymbolAddress((void**)&h2b,     g_h2b);
    cudaGetSymbolAddress((void**)&wvb,     g_wvb);
    cudaGetSymbolAddress((void**)&woutb,   g_woutb);
    cudaGetSymbolAddress((void**)&w1b,     g_w1b);
    cudaGetSymbolAddress((void**)&w2b,     g_w2b);

    cudaFuncSetAttribute(hgemm_kernel<0>, cudaFuncAttributeMaxDynamicSharedMemorySize, PSMEM);
    cudaFuncSetAttribute(hgemm_kernel<1>, cudaFuncAttributeMaxDynamicSharedMemorySize, PSMEM);
    cudaFuncSetAttribute(hgemm_kernel<2>, cudaFuncAttributeMaxDynamicSharedMemorySize, PSMEM);

    // weight prep
    f2bf_all_kernel<<<(655360 + 255) / 256, 256>>>(w_v, w_out, w1, w2, wvb, woutb, w1b, w2b);
    wcat_kernel<<<(256 * 216 + 255) / 256, 256>>>(w_off, w_attn, b_off, b_attn, wcat, bcat);

    // 1. LN1 -> xn (f32) + xnb (bf16)
    ln_kernel<<<NTOK, 256>>>(x, ln1_g, ln1_b, xn, xnb);
    // 2. v projection (bf16 TC)
    hgemm_kernel<0><<<dim3(256 / PBN, NTOK / PBM), 256, PSMEM>>>(xnb, wvb, b_v, nullptr, vb, 256, 256);
    // 3. offsets+attn combined (fp32)
    sgemm_kernel<<<dim3((216 + BN - 1) / BN, NTOK / BM), 256>>>(xn, wcat, bcat, offattn, 216, 256);
    // 4. softmax + bilinear sampling + aggregation
    sample_kernel<<<NTOK, 256>>>(vb, offattn, rp, aggb);
    // 5. output proj + residual -> xres (f32)
    hgemm_kernel<2><<<dim3(256 / PBN, NTOK / PBM), 256, PSMEM>>>(aggb, woutb, b_out, x, xres, 256, 256);
    // 6. LN2 -> yb (bf16)
    ln_kernel<<<NTOK, 256>>>(xres, ln2_g, ln2_b, nullptr, yb);
    // 7. fc1 + GELU (bf16 TC)
    hgemm_kernel<1><<<dim3(HID / PBN, NTOK / PBM), 256, PSMEM>>>(yb, w1b, b1, nullptr, hb, HID, 256);
    // 8. depthwise conv + GELU (sliding window)
    dwconv_kernel<<<dim3(2, 64, 2), 256>>>(hb, w_dw, b_dw, h2b);
    // 9. fc2 + residual -> out (f32)
    hgemm_kernel<2><<<dim3(256 / PBN, NTOK / PBM), 256, PSMEM>>>(h2b, w2b, b2, xres, out, 256, 1024);
}

// round 5
// speedup vs baseline: 2.6427x; 1.2031x over previous
#include <cuda_runtime.h>
#include <cuda_bf16.h>
#include <math.h>
#include <stdint.h>

typedef __nv_bfloat16 bf16;

#define NTOK 16384
#define CDIM 256
#define HID  1024

// -------- scratch (__device__ globals; no allocations allowed) --------
__device__ float g_xn     [NTOK * CDIM];
__device__ float g_offattn[NTOK * 256];
__device__ float g_xres   [NTOK * CDIM];
__device__ bf16  g_xnb    [NTOK * CDIM];
__device__ bf16  g_vb     [NTOK * CDIM];
__device__ bf16  g_aggb   [NTOK * CDIM];
__device__ bf16  g_yb     [NTOK * CDIM];
__device__ bf16  g_hb     [NTOK * HID];
__device__ bf16  g_h2b    [NTOK * HID];
__device__ bf16  g_wvb    [256 * 256];
__device__ bf16  g_woutb  [256 * 256];
__device__ bf16  g_w1b    [256 * 1024];
__device__ bf16  g_w2b    [1024 * 256];
__device__ float g_wcat   [256 * 256];
__device__ float g_bcat   [256];

__device__ __forceinline__ float gelu_f(float v) {
    return 0.5f * v * (1.0f + erff(v * 0.7071067811865476f));
}

__device__ __forceinline__ uint32_t smem_u32(const void* p) {
    uint32_t a;
    asm("{ .reg .u64 t; cvta.to.shared.u64 t, %1; cvt.u32.u64 %0, t; }" : "=r"(a) : "l"(p));
    return a;
}

__device__ __forceinline__ uint32_t f2tf32(float f) {
    uint32_t r;
    asm("cvt.rna.tf32.f32 %0, %1;" : "=r"(r) : "f"(f));
    return r;
}

// ---------------- merged weight prep ----------------
__global__ void prep_kernel(const float* wv, const float* wout, const float* w1,
                            const float* w2, const float* w_off, const float* w_attn,
                            const float* b_off, const float* b_attn,
                            bf16* wvb, bf16* woutb, bf16* w1b, bf16* w2b,
                            float* wcat, float* bcat) {
    int i = blockIdx.x * 256 + threadIdx.x;
    if (i < 65536) { wvb[i] = __float2bfloat16(wv[i]); return; }
    i -= 65536;
    if (i < 65536) { woutb[i] = __float2bfloat16(wout[i]); return; }
    i -= 65536;
    if (i < 262144) { w1b[i] = __float2bfloat16(w1[i]); return; }
    i -= 262144;
    if (i < 262144) { w2b[i] = __float2bfloat16(w2[i]); return; }
    i -= 262144;
    if (i < 65536) {
        int k = i >> 8, col = i & 255;
        float v = (col < 144) ? w_off[k * 144 + col]
                : (col < 216) ? w_attn[k * 72 + (col - 144)] : 0.f;
        wcat[i] = v;
        if (k == 0)
            bcat[col] = (col < 144) ? b_off[col]
                      : (col < 216) ? b_attn[col - 144] : 0.f;
    }
}

// ---------------- LayerNorm: one block per token, dual output ----------------
__global__ void ln_kernel(const float* __restrict__ x, const float* __restrict__ g,
                          const float* __restrict__ b, float* __restrict__ yf,
                          bf16* __restrict__ yb) {
    int tok = blockIdx.x;
    int c = threadIdx.x;
    float v = x[(size_t)tok * CDIM + c];
    __shared__ float sh[8];
    float s = v;
    #pragma unroll
    for (int o = 16; o; o >>= 1) s += __shfl_xor_sync(0xffffffffu, s, o);
    if ((c & 31) == 0) sh[c >> 5] = s;
    __syncthreads();
    float tot = 0.f;
    #pragma unroll
    for (int i = 0; i < 8; ++i) tot += sh[i];
    float mean = tot * (1.0f / CDIM);
    __syncthreads();
    float d = v - mean;
    float s2 = d * d;
    #pragma unroll
    for (int o = 16; o; o >>= 1) s2 += __shfl_xor_sync(0xffffffffu, s2, o);
    if ((c & 31) == 0) sh[c >> 5] = s2;
    __syncthreads();
    float v2 = 0.f;
    #pragma unroll
    for (int i = 0; i < 8; ++i) v2 += sh[i];
    float var = v2 * (1.0f / CDIM);
    float out = d * rsqrtf(var + 1e-5f) * g[c] + b[c];
    if (yf) yf[(size_t)tok * CDIM + c] = out;
    if (yb) yb[(size_t)tok * CDIM + c] = __float2bfloat16(out);
}

// ---------------- tf32 GEMM for off/attn: 64x256x16 tile, 3-stage ------------
// A = xn (f32 [M,256]), B = wcat (f32 [256,256]); out f32 [M,256] + bias.
#define TFA_STR 20     // f32 per A smem row
#define TFB_STR 264    // f32 per B smem row
#define TFA_SZ  (64 * TFA_STR * 4)          // 5120 B
#define TFB_SZ  (16 * TFB_STR * 4)          // 16896 B
#define TF_STG  (TFA_SZ + TFB_SZ)           // 22016 B
#define TF_SMEM (3 * TF_STG)                // 66048 B

__global__ __launch_bounds__(256)
void tgemm_offattn(const float* __restrict__ A, const float* __restrict__ Bw,
                   const float* __restrict__ bias, float* __restrict__ C) {
    extern __shared__ char sm_[];
    uint32_t S0 = smem_u32(sm_);
    int t = threadIdx.x;
    int lane = t & 31, warp = t >> 5;
    int wm = (warp & 1) * 32;
    int wn = (warp >> 1) * 64;
    int m0 = blockIdx.x * 64;

    // global->smem mapping
    int a_row = t >> 2, a_c4 = (t & 3) * 4;
    const float* Ag = A + (size_t)(m0 + a_row) * 256 + a_c4;
    uint32_t a_s = S0 + (a_row * TFA_STR + a_c4) * 4;

    auto prefetch = [&](int it) {
        int st = it % 3;
        const float* ag = Ag + it * 16;
        asm volatile("cp.async.cg.shared.global [%0], [%1], 16;"
                     :: "r"(a_s + st * TF_STG), "l"(ag));
        #pragma unroll
        for (int i = 0; i < 4; ++i) {
            int idx = t + i * 256;
            int row = idx >> 6, c4 = (idx & 63) * 4;
            const float* bg = Bw + (size_t)(it * 16 + row) * 256 + c4;
            uint32_t dst = S0 + TFA_SZ + (row * TFB_STR + c4) * 4 + st * TF_STG;
            asm volatile("cp.async.cg.shared.global [%0], [%1], 16;" :: "r"(dst), "l"(bg));
        }
        asm volatile("cp.async.commit_group;");
    };

    float acc[2][8][4];
    #pragma unroll
    for (int mi = 0; mi < 2; ++mi)
        #pragma unroll
        for (int nj = 0; nj < 8; ++nj)
            #pragma unroll
            for (int r = 0; r < 4; ++r) acc[mi][nj][r] = 0.f;

    const int niter = 16;
    prefetch(0); prefetch(1);

    int lr = lane >> 2, lc = lane & 3;
    for (int it = 0; it < niter; ++it) {
        if (it + 1 < niter) asm volatile("cp.async.wait_group 1;");
        else                asm volatile("cp.async.wait_group 0;");
        __syncthreads();
        if (it + 2 < niter) prefetch(it + 2);

        const float* As = (const float*)(sm_ + (it % 3) * TF_STG);
        const float* Bs = (const float*)(sm_ + (it % 3) * TF_STG + TFA_SZ);

        #pragma unroll
        for (int kk = 0; kk < 2; ++kk) {
            uint32_t af[2][4];
            #pragma unroll
            for (int mi = 0; mi < 2; ++mi) {
                int rb = wm + mi * 16 + lr;
                af[mi][0] = f2tf32(As[rb * TFA_STR + kk * 8 + lc]);
                af[mi][1] = f2tf32(As[(rb + 8) * TFA_STR + kk * 8 + lc]);
                af[mi][2] = f2tf32(As[rb * TFA_STR + kk * 8 + lc + 4]);
                af[mi][3] = f2tf32(As[(rb + 8) * TFA_STR + kk * 8 + lc + 4]);
            }
            #pragma unroll
            for (int nj = 0; nj < 8; ++nj) {
                uint32_t b0 = f2tf32(Bs[(kk * 8 + lc) * TFB_STR + wn + nj * 8 + lr]);
                uint32_t b1 = f2tf32(Bs[(kk * 8 + lc + 4) * TFB_STR + wn + nj * 8 + lr]);
                #pragma unroll
                for (int mi = 0; mi < 2; ++mi)
                    asm volatile(
                        "mma.sync.aligned.m16n8k8.row.col.f32.tf32.tf32.f32 "
                        "{%0,%1,%2,%3}, {%4,%5,%6,%7}, {%8,%9}, {%0,%1,%2,%3};"
                        : "+f"(acc[mi][nj][0]), "+f"(acc[mi][nj][1]),
                          "+f"(acc[mi][nj][2]), "+f"(acc[mi][nj][3])
                        : "r"(af[mi][0]), "r"(af[mi][1]), "r"(af[mi][2]), "r"(af[mi][3]),
                          "r"(b0), "r"(b1));
            }
        }
    }

    #pragma unroll
    for (int mi = 0; mi < 2; ++mi) {
        #pragma unroll
        for (int nj = 0; nj < 8; ++nj) {
            int r = m0 + wm + mi * 16 + lr;
            int c = wn + nj * 8 + lc * 2;
            float bx = bias[c], by = bias[c + 1];
            float2 v0 = {acc[mi][nj][0] + bx, acc[mi][nj][1] + by};
            float2 v1 = {acc[mi][nj][2] + bx, acc[mi][nj][3] + by};
            *(float2*)(C + (size_t)r * 256 + c) = v0;
            *(float2*)(C + (size_t)(r + 8) * 256 + c) = v1;
        }
    }
}

// ---------------- bf16 mma.sync GEMM: 128x128x32, 3-stage, single sync -------
#define PBM 128
#define PBN 128
#define PBK 32
#define PASTR 80
#define PBSTR 272
#define PA_ST (PBM * PASTR)
#define PB_ST (PBK * PBSTR)
#define PSTG  (PA_ST + PB_ST)
#define PSMEM (3 * PSTG)

template<int EPI>
__global__ __launch_bounds__(256)
void hgemm_kernel(const bf16* __restrict__ A, const bf16* __restrict__ B,
                  const float* __restrict__ bias, const float* __restrict__ resid,
                  void* __restrict__ Cp, int N, int K) {
    extern __shared__ char sm_[];
    uint32_t S0 = smem_u32(sm_);

    int t = threadIdx.x;
    int lane = t & 31, warp = t >> 5;
    int wm = (warp & 3) * 32;
    int wn = (warp >> 2) * 64;
    int m0 = blockIdx.y * PBM;
    int n0 = blockIdx.x * PBN;

    int a_row = t >> 1;
    int a_c16 = (t & 1) * 2;
    const bf16* Ag = A + (size_t)(m0 + a_row) * K + a_c16 * 8;
    uint32_t a_s = S0 + a_row * PASTR + a_c16 * 16;
    int b_row = t >> 3;
    int b_c16 = (t & 7) * 2;
    const bf16* Bg = B + (size_t)b_row * N + n0 + b_c16 * 8;
    uint32_t b_s = S0 + PA_ST + b_row * PBSTR + b_c16 * 16;

    auto prefetch = [&](int chunk) {
        int st = chunk % 3;
        const bf16* ag = Ag + chunk * PBK;
        const bf16* bg = Bg + (size_t)chunk * PBK * N;
        uint32_t sa = a_s + st * PSTG;
        uint32_t sb = b_s + st * PSTG;
        asm volatile("cp.async.cg.shared.global [%0], [%1], 16;" :: "r"(sa), "l"(ag));
        asm volatile("cp.async.cg.shared.global [%0], [%1], 16;" :: "r"(sa + 16), "l"(ag + 8));
        asm volatile("cp.async.cg.shared.global [%0], [%1], 16;" :: "r"(sb), "l"(bg));
        asm volatile("cp.async.cg.shared.global [%0], [%1], 16;" :: "r"(sb + 16), "l"(bg + 8));
        asm volatile("cp.async.commit_group;");
    };

    uint32_t aoff[2], boff[4];
    #pragma unroll
    for (int mi = 0; mi < 2; ++mi)
        aoff[mi] = (wm + mi * 16 + (lane & 15)) * PASTR + (lane >> 4) * 16;
    int tile = lane >> 3;
    #pragma unroll
    for (int ni = 0; ni < 4; ++ni)
        boff[ni] = PA_ST + ((tile & 1) * 8 + (lane & 7)) * PBSTR
                 + (wn + ni * 16 + (tile >> 1) * 8) * 2;

    float acc[2][8][4];
    #pragma unroll
    for (int mi = 0; mi < 2; ++mi)
        #pragma unroll
        for (int nj = 0; nj < 8; ++nj)
            #pragma unroll
            for (int r = 0; r < 4; ++r) acc[mi][nj][r] = 0.f;

    int niter = K / PBK;
    prefetch(0);
    prefetch(1);

    for (int it = 0; it < niter; ++it) {
        if (it + 1 < niter) asm volatile("cp.async.wait_group 1;");
        else                asm volatile("cp.async.wait_group 0;");
        __syncthreads();
        if (it + 2 < niter) prefetch(it + 2);

        uint32_t Sb = S0 + (it % 3) * PSTG;
        #pragma unroll
        for (int kk = 0; kk < 2; ++kk) {
            uint32_t a[2][4];
            #pragma unroll
            for (int mi = 0; mi < 2; ++mi) {
                uint32_t addr = Sb + aoff[mi] + kk * 32;
                asm volatile("ldmatrix.sync.aligned.m8n8.x4.shared.b16 {%0,%1,%2,%3}, [%4];"
                    : "=r"(a[mi][0]), "=r"(a[mi][1]), "=r"(a[mi][2]), "=r"(a[mi][3]) : "r"(addr));
            }
            uint32_t bq[4][4];
            #pragma unroll
            for (int ni = 0; ni < 4; ++ni) {
                uint32_t addr = Sb + boff[ni] + kk * 16 * PBSTR;
                asm volatile("ldmatrix.sync.aligned.m8n8.x4.trans.shared.b16 {%0,%1,%2,%3}, [%4];"
                    : "=r"(bq[ni][0]), "=r"(bq[ni][1]), "=r"(bq[ni][2]), "=r"(bq[ni][3]) : "r"(addr));
            }
            #pragma unroll
            for (int mi = 0; mi < 2; ++mi)
                #pragma unroll
                for (int nj = 0; nj < 8; ++nj) {
                    uint32_t b0 = bq[nj >> 1][(nj & 1) * 2];
                    uint32_t b1 = bq[nj >> 1][(nj & 1) * 2 + 1];
                    asm volatile(
                        "mma.sync.aligned.m16n8k16.row.col.f32.bf16.bf16.f32 "
                        "{%0,%1,%2,%3}, {%4,%5,%6,%7}, {%8,%9}, {%0,%1,%2,%3};"
                        : "+f"(acc[mi][nj][0]), "+f"(acc[mi][nj][1]),
                          "+f"(acc[mi][nj][2]), "+f"(acc[mi][nj][3])
                        : "r"(a[mi][0]), "r"(a[mi][1]), "r"(a[mi][2]), "r"(a[mi][3]),
                          "r"(b0), "r"(b1));
                }
        }
    }

    int r_base = m0 + wm + (lane >> 2);
    int c_base = n0 + wn + (lane & 3) * 2;
    #pragma unroll
    for (int mi = 0; mi < 2; ++mi) {
        #pragma unroll
        for (int nj = 0; nj < 8; ++nj) {
            int r = r_base + mi * 16;
            int c = c_base + nj * 8;
            float bx = bias[c], by = bias[c + 1];
            float o00 = acc[mi][nj][0] + bx;
            float o01 = acc[mi][nj][1] + by;
            float o10 = acc[mi][nj][2] + bx;
            float o11 = acc[mi][nj][3] + by;
            if (EPI == 1) {
                o00 = gelu_f(o00); o01 = gelu_f(o01);
                o10 = gelu_f(o10); o11 = gelu_f(o11);
            }
            if (EPI == 2) {
                const float* rp0 = resid + (size_t)r * N + c;
                const float* rp1 = resid + (size_t)(r + 8) * N + c;
                float* Cf = (float*)Cp;
                float2 v0 = {o00 + rp0[0], o01 + rp0[1]};
                float2 v1 = {o10 + rp1[0], o11 + rp1[1]};
                *(float2*)(Cf + (size_t)r * N + c) = v0;
                *(float2*)(Cf + (size_t)(r + 8) * N + c) = v1;
            } else {
                bf16* Cb = (bf16*)Cp;
                __nv_bfloat162 v0 = {__float2bfloat16(o00), __float2bfloat16(o01)};
                __nv_bfloat162 v1 = {__float2bfloat16(o10), __float2bfloat16(o11)};
                *(__nv_bfloat162*)(Cb + (size_t)r * N + c) = v0;
                *(__nv_bfloat162*)(Cb + (size_t)(r + 8) * N + c) = v1;
            }
        }
    }
}

// ---------------- Deformable sampling + softmax + aggregation ----------------
__global__ void sample_kernel(const bf16* __restrict__ v, const float* __restrict__ offattn,
                              const float* __restrict__ rp, bf16* __restrict__ agg) {
    int gw = blockIdx.x * 8 + (threadIdx.x >> 5);
    int lane = threadIdx.x & 31;
    int head = gw & 7;
    int tg = gw >> 3;
    int bb = tg >> 13;
    int pos = tg & 8191;

    const float* lg = offattn + (size_t)tg * 256 + 144 + head * 9;
    float w[9];
    float mx = -1e30f;
    #pragma unroll
    for (int k = 0; k < 9; ++k) { w[k] = lg[k]; mx = fmaxf(mx, w[k]); }
    float sum = 0.f;
    #pragma unroll
    for (int k = 0; k < 9; ++k) { w[k] = expf(w[k] - mx); sum += w[k]; }
    float inv = 1.0f / sum;

    const float* rpp  = rp + (size_t)pos * 18;
    const float* offp = offattn + (size_t)tg * 256 + head * 18;
    const bf16* vc = v + head * 32 + lane;
    int base = bb << 13;
    float acc = 0.f;
    #pragma unroll
    for (int k = 0; k < 9; ++k) {
        float cx = (rpp[k * 2 + 0] + offp[k * 2 + 0] + 1.0f) * 0.5f * 127.0f;
        float cy = (rpp[k * 2 + 1] + offp[k * 2 + 1] + 1.0f) * 0.5f * 63.0f;
        float fx = floorf(cx), fy = floorf(cy);
        float wx = cx - fx, wy = cy - fy;
        int x0 = min(max((int)fx, 0), 127);
        int x1 = min(max((int)fx + 1, 0), 127);
        int y0 = min(max((int)fy, 0), 63);
        int y1 = min(max((int)fy + 1, 0), 63);
        float v00 = __bfloat162float(vc[(size_t)(base + y0 * 128 + x0) * 256]);
        float v01 = __bfloat162float(vc[(size_t)(base + y0 * 128 + x1) * 256]);
        float v10 = __bfloat162float(vc[(size_t)(base + y1 * 128 + x0) * 256]);
        float v11 = __bfloat162float(vc[(size_t)(base + y1 * 128 + x1) * 256]);
        float s = v00 * (1.f - wy) * (1.f - wx) + v01 * (1.f - wy) * wx
                + v10 * wy * (1.f - wx) + v11 * wy * wx;
        acc += s * (w[k] * inv);
    }
    agg[(size_t)tg * 256 + head * 32 + lane] = __float2bfloat16(acc);
}

// ---------------- Depthwise 3x3 conv: sliding window, 4-way x-split ----------
__global__ void dwconv_kernel(const bf16* __restrict__ h, const float* __restrict__ wdw,
                              const float* __restrict__ bdw, bf16* __restrict__ o) {
    int c2 = blockIdx.x * 256 + threadIdx.x;
    int y = blockIdx.y & 63;
    int seg = blockIdx.y >> 6;     // 0..3
    int bb = blockIdx.z;
    int c = c2 * 2;
    int x0 = seg * 32;

    float w0[9], w1[9];
    #pragma unroll
    for (int i = 0; i < 9; ++i) { w0[i] = wdw[c * 9 + i]; w1[i] = wdw[(c + 1) * 9 + i]; }
    float bb0 = bdw[c], bb1 = bdw[c + 1];

    const __nv_bfloat162* hp = (const __nv_bfloat162*)h;
    size_t base = ((size_t)(bb << 13) + y * 128) * 512 + c2;
    bool hu = (y > 0), hd = (y < 63);
    __nv_bfloat162 zero = __float2bfloat162_rn(0.f);

    __nv_bfloat162 cm[3], cc[3], cn[3];
    {
        size_t p = base + ((x0 + 127) & 127) * 512;
        cm[0] = hu ? hp[p - 65536] : zero; cm[1] = hp[p]; cm[2] = hd ? hp[p + 65536] : zero;
        p = base + x0 * 512;
        cc[0] = hu ? hp[p - 65536] : zero; cc[1] = hp[p]; cc[2] = hd ? hp[p + 65536] : zero;
    }
    bf16* op = o + ((size_t)(bb << 13) + y * 128) * 1024 + c;

    for (int x = x0; x < x0 + 32; ++x) {
        size_t p = base + ((x + 1) & 127) * 512;
        cn[0] = hu ? hp[p - 65536] : zero; cn[1] = hp[p]; cn[2] = hd ? hp[p + 65536] : zero;

        float a0 = bb0, a1 = bb1;
        #pragma unroll
        for (int dy = 0; dy < 3; ++dy) {
            float2 vm = __bfloat1622float2(cm[dy]);
            float2 vc = __bfloat1622float2(cc[dy]);
            float2 vp = __bfloat1622float2(cn[dy]);
            a0 += vm.x * w0[dy * 3 + 0] + vc.x * w0[dy * 3 + 1] + vp.x * w0[dy * 3 + 2];
            a1 += vm.y * w1[dy * 3 + 0] + vc.y * w1[dy * 3 + 1] + vp.y * w1[dy * 3 + 2];
        }
        __nv_bfloat162 ov = {__float2bfloat16(gelu_f(a0)), __float2bfloat16(gelu_f(a1))};
        *(__nv_bfloat162*)(op + (size_t)x * 1024) = ov;

        #pragma unroll
        for (int i = 0; i < 3; ++i) { cm[i] = cc[i]; cc[i] = cn[i]; }
    }
}

// ---------------- launch ----------------
extern "C" void kernel_launch(void* const* d_in, const int* in_sizes, int n_in,
                              void* d_out, int out_size) {
    const float* x      = (const float*)d_in[0];
    const float* rp     = (const float*)d_in[1];
    const float* ln1_g  = (const float*)d_in[2];
    const float* ln1_b  = (const float*)d_in[3];
    const float* w_v    = (const float*)d_in[4];
    const float* b_v    = (const float*)d_in[5];
    const float* w_off  = (const float*)d_in[6];
    const float* b_off  = (const float*)d_in[7];
    const float* w_attn = (const float*)d_in[8];
    const float* b_attn = (const float*)d_in[9];
    const float* w_out  = (const float*)d_in[10];
    const float* b_out  = (const float*)d_in[11];
    const float* ln2_g  = (const float*)d_in[12];
    const float* ln2_b  = (const float*)d_in[13];
    const float* w1     = (const float*)d_in[14];
    const float* b1     = (const float*)d_in[15];
    const float* w_dw   = (const float*)d_in[16];
    const float* b_dw   = (const float*)d_in[17];
    const float* w2     = (const float*)d_in[18];
    const float* b2     = (const float*)d_in[19];
    float* out = (float*)d_out;

    float *xn, *offattn, *xres, *wcat, *bcat;
    bf16 *xnb, *vb, *aggb, *yb, *hb, *h2b, *wvb, *woutb, *w1b, *w2b;
    cudaGetSymbolAddress((void**)&xn,      g_xn);
    cudaGetSymbolAddress((void**)&offattn, g_offattn);
    cudaGetSymbolAddress((void**)&xres,    g_xres);
    cudaGetSymbolAddress((void**)&wcat,    g_wcat);
    cudaGetSymbolAddress((void**)&bcat,    g_bcat);
    cudaGetSymbolAddress((void**)&xnb,     g_xnb);
    cudaGetSymbolAddress((void**)&vb,      g_vb);
    cudaGetSymbolAddress((void**)&aggb,    g_aggb);
    cudaGetSymbolAddress((void**)&yb,      g_yb);
    cudaGetSymbolAddress((void**)&hb,      g_hb);
    cudaGetSymbolAddress((void**)&h2b,     g_h2b);
    cudaGetSymbolAddress((void**)&wvb,     g_wvb);
    cudaGetSymbolAddress((void**)&woutb,   g_woutb);
    cudaGetSymbolAddress((void**)&w1b,     g_w1b);
    cudaGetSymbolAddress((void**)&w2b,     g_w2b);

    cudaFuncSetAttribute(hgemm_kernel<0>, cudaFuncAttributeMaxDynamicSharedMemorySize, PSMEM);
    cudaFuncSetAttribute(hgemm_kernel<1>, cudaFuncAttributeMaxDynamicSharedMemorySize, PSMEM);
    cudaFuncSetAttribute(hgemm_kernel<2>, cudaFuncAttributeMaxDynamicSharedMemorySize, PSMEM);
    cudaFuncSetAttribute(tgemm_offattn,   cudaFuncAttributeMaxDynamicSharedMemorySize, TF_SMEM);

    // weight prep (single kernel)
    prep_kernel<<<(655360 + 65536 + 255) / 256, 256>>>(
        w_v, w_out, w1, w2, w_off, w_attn, b_off, b_attn,
        wvb, woutb, w1b, w2b, wcat, bcat);

    // 1. LN1 -> xn (f32) + xnb (bf16)
    ln_kernel<<<NTOK, 256>>>(x, ln1_g, ln1_b, xn, xnb);
    // 2. v projection (bf16 TC)
    hgemm_kernel<0><<<dim3(256 / PBN, NTOK / PBM), 256, PSMEM>>>(xnb, wvb, b_v, nullptr, vb, 256, 256);
    // 3. offsets+attn combined (tf32 TC)
    tgemm_offattn<<<NTOK / 64, 256, TF_SMEM>>>(xn, wcat, bcat, offattn);
    // 4. softmax + bilinear sampling + aggregation
    sample_kernel<<<NTOK, 256>>>(vb, offattn, rp, aggb);
    // 5. output proj + residual -> xres (f32)
    hgemm_kernel<2><<<dim3(256 / PBN, NTOK / PBM), 256, PSMEM>>>(aggb, woutb, b_out, x, xres, 256, 256);
    // 6. LN2 -> yb (bf16)
    ln_kernel<<<NTOK, 256>>>(xres, ln2_g, ln2_b, nullptr, yb);
    // 7. fc1 + GELU (bf16 TC)
    hgemm_kernel<1><<<dim3(HID / PBN, NTOK / PBM), 256, PSMEM>>>(yb, w1b, b1, nullptr, hb, HID, 256);
    // 8. depthwise conv + GELU (sliding window, x-split)
    dwconv_kernel<<<dim3(2, 256, 2), 256>>>(hb, w_dw, b_dw, h2b);
    // 9. fc2 + residual -> out (f32)
    hgemm_kernel<2><<<dim3(256 / PBN, NTOK / PBM), 256, PSMEM>>>(h2b, w2b, b2, xres, out, 256, 1024);
}

// round 7
// speedup vs baseline: 3.0066x; 1.1377x over previous
#include <cuda_runtime.h>
#include <cuda_bf16.h>
#include <math.h>
#include <stdint.h>

typedef __nv_bfloat16 bf16;

#define NTOK 16384
#define CDIM 256
#define HID  1024

// -------- scratch (__device__ globals; no allocations allowed) --------
__device__ float g_xn     [NTOK * CDIM];
__device__ float g_offattn[NTOK * 256];
__device__ float g_xres   [NTOK * CDIM];
__device__ bf16  g_xnb    [NTOK * CDIM];
__device__ bf16  g_vb     [NTOK * CDIM];
__device__ bf16  g_aggb   [NTOK * CDIM];
__device__ bf16  g_yb     [NTOK * CDIM];
__device__ bf16  g_hb     [NTOK * HID];
__device__ bf16  g_h2b    [NTOK * HID];
__device__ bf16  g_wvb    [256 * 256];
__device__ bf16  g_woutb  [256 * 256];
__device__ bf16  g_w1b    [256 * 1024];
__device__ bf16  g_w2b    [1024 * 256];
__device__ float g_wcat   [256 * 256];
__device__ float g_bcat   [256];

__device__ __forceinline__ float gelu_f(float v) {
    return 0.5f * v * (1.0f + erff(v * 0.7071067811865476f));
}

__device__ __forceinline__ uint32_t smem_u32(const void* p) {
    uint32_t a;
    asm("{ .reg .u64 t; cvta.to.shared.u64 t, %1; cvt.u32.u64 %0, t; }" : "=r"(a) : "l"(p));
    return a;
}

__device__ __forceinline__ uint32_t f2tf32(float f) {
    uint32_t r;
    asm("cvt.rna.tf32.f32 %0, %1;" : "=r"(r) : "f"(f));
    return r;
}

// ---------------- merged weight prep (wcat pre-rounded to tf32) --------------
__global__ void prep_kernel(const float* wv, const float* wout, const float* w1,
                            const float* w2, const float* w_off, const float* w_attn,
                            const float* b_off, const float* b_attn,
                            bf16* wvb, bf16* woutb, bf16* w1b, bf16* w2b,
                            float* wcat, float* bcat) {
    int i = blockIdx.x * 256 + threadIdx.x;
    if (i < 65536) { wvb[i] = __float2bfloat16(wv[i]); return; }
    i -= 65536;
    if (i < 65536) { woutb[i] = __float2bfloat16(wout[i]); return; }
    i -= 65536;
    if (i < 262144) { w1b[i] = __float2bfloat16(w1[i]); return; }
    i -= 262144;
    if (i < 262144) { w2b[i] = __float2bfloat16(w2[i]); return; }
    i -= 262144;
    if (i < 65536) {
        int k = i >> 8, col = i & 255;
        float v = (col < 144) ? w_off[k * 144 + col]
                : (col < 216) ? w_attn[k * 72 + (col - 144)] : 0.f;
        wcat[i] = __uint_as_float(f2tf32(v));
        if (k == 0)
            bcat[col] = (col < 144) ? b_off[col]
                      : (col < 216) ? b_attn[col - 144] : 0.f;
    }
}

// ---------------- LayerNorm: one block per token, dual output ----------------
// TF32R: round the f32 output to tf32 (only when its sole consumer is tgemm)
template<bool TF32R>
__global__ void ln_kernel(const float* __restrict__ x, const float* __restrict__ g,
                          const float* __restrict__ b, float* __restrict__ yf,
                          bf16* __restrict__ yb) {
    int tok = blockIdx.x;
    int c = threadIdx.x;
    float v = x[(size_t)tok * CDIM + c];
    __shared__ float sh[8];
    float s = v;
    #pragma unroll
    for (int o = 16; o; o >>= 1) s += __shfl_xor_sync(0xffffffffu, s, o);
    if ((c & 31) == 0) sh[c >> 5] = s;
    __syncthreads();
    float tot = 0.f;
    #pragma unroll
    for (int i = 0; i < 8; ++i) tot += sh[i];
    float mean = tot * (1.0f / CDIM);
    __syncthreads();
    float d = v - mean;
    float s2 = d * d;
    #pragma unroll
    for (int o = 16; o; o >>= 1) s2 += __shfl_xor_sync(0xffffffffu, s2, o);
    if ((c & 31) == 0) sh[c >> 5] = s2;
    __syncthreads();
    float v2 = 0.f;
    #pragma unroll
    for (int i = 0; i < 8; ++i) v2 += sh[i];
    float var = v2 * (1.0f / CDIM);
    float out = d * rsqrtf(var + 1e-5f) * g[c] + b[c];
    if (yf) yf[(size_t)tok * CDIM + c] = TF32R ? __uint_as_float(f2tf32(out)) : out;
    if (yb) yb[(size_t)tok * CDIM + c] = __float2bfloat16(out);
}

// ---------------- tf32 GEMM for off/attn: 64x256x16 tile, 3-stage ------------
// Inputs already tf32-rounded in f32 containers — no cvt in the hot loop.
#define TFA_STR 20
#define TFB_STR 264
#define TFA_SZ  (64 * TFA_STR * 4)
#define TFB_SZ  (16 * TFB_STR * 4)
#define TF_STG  (TFA_SZ + TFB_SZ)
#define TF_SMEM (3 * TF_STG)

__global__ __launch_bounds__(256)
void tgemm_offattn(const float* __restrict__ A, const float* __restrict__ Bw,
                   const float* __restrict__ bias, float* __restrict__ C) {
    extern __shared__ char sm_[];
    uint32_t S0 = smem_u32(sm_);
    int t = threadIdx.x;
    int lane = t & 31, warp = t >> 5;
    int wm = (warp & 1) * 32;
    int wn = (warp >> 1) * 64;
    int m0 = blockIdx.x * 64;

    int a_row = t >> 2, a_c4 = (t & 3) * 4;
    const float* Ag = A + (size_t)(m0 + a_row) * 256 + a_c4;
    uint32_t a_s = S0 + (a_row * TFA_STR + a_c4) * 4;

    auto prefetch = [&](int it) {
        int st = it % 3;
        const float* ag = Ag + it * 16;
        asm volatile("cp.async.cg.shared.global [%0], [%1], 16;"
                     :: "r"(a_s + st * TF_STG), "l"(ag));
        #pragma unroll
        for (int i = 0; i < 4; ++i) {
            int idx = t + i * 256;
            int row = idx >> 6, c4 = (idx & 63) * 4;
            const float* bg = Bw + (size_t)(it * 16 + row) * 256 + c4;
            uint32_t dst = S0 + TFA_SZ + (row * TFB_STR + c4) * 4 + st * TF_STG;
            asm volatile("cp.async.cg.shared.global [%0], [%1], 16;" :: "r"(dst), "l"(bg));
        }
        asm volatile("cp.async.commit_group;");
    };

    float acc[2][8][4];
    #pragma unroll
    for (int mi = 0; mi < 2; ++mi)
        #pragma unroll
        for (int nj = 0; nj < 8; ++nj)
            #pragma unroll
            for (int r = 0; r < 4; ++r) acc[mi][nj][r] = 0.f;

    const int niter = 16;
    prefetch(0); prefetch(1);

    int lr = lane >> 2, lc = lane & 3;
    for (int it = 0; it < niter; ++it) {
        if (it + 1 < niter) asm volatile("cp.async.wait_group 1;");
        else                asm volatile("cp.async.wait_group 0;");
        __syncthreads();
        if (it + 2 < niter) prefetch(it + 2);

        const uint32_t* As = (const uint32_t*)(sm_ + (it % 3) * TF_STG);
        const uint32_t* Bs = (const uint32_t*)(sm_ + (it % 3) * TF_STG + TFA_SZ);

        #pragma unroll
        for (int kk = 0; kk < 2; ++kk) {
            uint32_t af[2][4];
            #pragma unroll
            for (int mi = 0; mi < 2; ++mi) {
                int rb = wm + mi * 16 + lr;
                af[mi][0] = As[rb * TFA_STR + kk * 8 + lc];
                af[mi][1] = As[(rb + 8) * TFA_STR + kk * 8 + lc];
                af[mi][2] = As[rb * TFA_STR + kk * 8 + lc + 4];
                af[mi][3] = As[(rb + 8) * TFA_STR + kk * 8 + lc + 4];
            }
            #pragma unroll
            for (int nj = 0; nj < 8; ++nj) {
                uint32_t b0 = Bs[(kk * 8 + lc) * TFB_STR + wn + nj * 8 + lr];
                uint32_t b1 = Bs[(kk * 8 + lc + 4) * TFB_STR + wn + nj * 8 + lr];
                #pragma unroll
                for (int mi = 0; mi < 2; ++mi)
                    asm volatile(
                        "mma.sync.aligned.m16n8k8.row.col.f32.tf32.tf32.f32 "
                        "{%0,%1,%2,%3}, {%4,%5,%6,%7}, {%8,%9}, {%0,%1,%2,%3};"
                        : "+f"(acc[mi][nj][0]), "+f"(acc[mi][nj][1]),
                          "+f"(acc[mi][nj][2]), "+f"(acc[mi][nj][3])
                        : "r"(af[mi][0]), "r"(af[mi][1]), "r"(af[mi][2]), "r"(af[mi][3]),
                          "r"(b0), "r"(b1));
            }
        }
    }

    #pragma unroll
    for (int mi = 0; mi < 2; ++mi) {
        #pragma unroll
        for (int nj = 0; nj < 8; ++nj) {
            int r = m0 + wm + mi * 16 + lr;
            int c = wn + nj * 8 + lc * 2;
            float bx = bias[c], by = bias[c + 1];
            float2 v0 = {acc[mi][nj][0] + bx, acc[mi][nj][1] + by};
            float2 v1 = {acc[mi][nj][2] + bx, acc[mi][nj][3] + by};
            *(float2*)(C + (size_t)r * 256 + c) = v0;
            *(float2*)(C + (size_t)(r + 8) * 256 + c) = v1;
        }
    }
}

// ---------------- bf16 mma.sync GEMM: 128x128x32, 3-stage, single sync -------
#define PBM 128
#define PBN 128
#define PBK 32
#define PASTR 80
#define PBSTR 272
#define PA_ST (PBM * PASTR)
#define PB_ST (PBK * PBSTR)
#define PSTG  (PA_ST + PB_ST)
#define PSMEM (3 * PSTG)

template<int EPI>
__global__ __launch_bounds__(256)
void hgemm_kernel(const bf16* __restrict__ A, const bf16* __restrict__ B,
                  const float* __restrict__ bias, const float* __restrict__ resid,
                  void* __restrict__ Cp, int N, int K) {
    extern __shared__ char sm_[];
    uint32_t S0 = smem_u32(sm_);

    int t = threadIdx.x;
    int lane = t & 31, warp = t >> 5;
    int wm = (warp & 3) * 32;
    int wn = (warp >> 2) * 64;
    int m0 = blockIdx.y * PBM;
    int n0 = blockIdx.x * PBN;

    int a_row = t >> 1;
    int a_c16 = (t & 1) * 2;
    const bf16* Ag = A + (size_t)(m0 + a_row) * K + a_c16 * 8;
    uint32_t a_s = S0 + a_row * PASTR + a_c16 * 16;
    int b_row = t >> 3;
    int b_c16 = (t & 7) * 2;
    const bf16* Bg = B + (size_t)b_row * N + n0 + b_c16 * 8;
    uint32_t b_s = S0 + PA_ST + b_row * PBSTR + b_c16 * 16;

    auto prefetch = [&](int chunk) {
        int st = chunk % 3;
        const bf16* ag = Ag + chunk * PBK;
        const bf16* bg = Bg + (size_t)chunk * PBK * N;
        uint32_t sa = a_s + st * PSTG;
        uint32_t sb = b_s + st * PSTG;
        asm volatile("cp.async.cg.shared.global [%0], [%1], 16;" :: "r"(sa), "l"(ag));
        asm volatile("cp.async.cg.shared.global [%0], [%1], 16;" :: "r"(sa + 16), "l"(ag + 8));
        asm volatile("cp.async.cg.shared.global [%0], [%1], 16;" :: "r"(sb), "l"(bg));
        asm volatile("cp.async.cg.shared.global [%0], [%1], 16;" :: "r"(sb + 16), "l"(bg + 8));
        asm volatile("cp.async.commit_group;");
    };

    uint32_t aoff[2], boff[4];
    #pragma unroll
    for (int mi = 0; mi < 2; ++mi)
        aoff[mi] = (wm + mi * 16 + (lane & 15)) * PASTR + (lane >> 4) * 16;
    int tile = lane >> 3;
    #pragma unroll
    for (int ni = 0; ni < 4; ++ni)
        boff[ni] = PA_ST + ((tile & 1) * 8 + (lane & 7)) * PBSTR
                 + (wn + ni * 16 + (tile >> 1) * 8) * 2;

    float acc[2][8][4];
    #pragma unroll
    for (int mi = 0; mi < 2; ++mi)
        #pragma unroll
        for (int nj = 0; nj < 8; ++nj)
            #pragma unroll
            for (int r = 0; r < 4; ++r) acc[mi][nj][r] = 0.f;

    int niter = K / PBK;
    prefetch(0);
    prefetch(1);

    for (int it = 0; it < niter; ++it) {
        if (it + 1 < niter) asm volatile("cp.async.wait_group 1;");
        else                asm volatile("cp.async.wait_group 0;");
        __syncthreads();
        if (it + 2 < niter) prefetch(it + 2);

        uint32_t Sb = S0 + (it % 3) * PSTG;
        #pragma unroll
        for (int kk = 0; kk < 2; ++kk) {
            uint32_t a[2][4];
            #pragma unroll
            for (int mi = 0; mi < 2; ++mi) {
                uint32_t addr = Sb + aoff[mi] + kk * 32;
                asm volatile("ldmatrix.sync.aligned.m8n8.x4.shared.b16 {%0,%1,%2,%3}, [%4];"
                    : "=r"(a[mi][0]), "=r"(a[mi][1]), "=r"(a[mi][2]), "=r"(a[mi][3]) : "r"(addr));
            }
            uint32_t bq[4][4];
            #pragma unroll
            for (int ni = 0; ni < 4; ++ni) {
                uint32_t addr = Sb + boff[ni] + kk * 16 * PBSTR;
                asm volatile("ldmatrix.sync.aligned.m8n8.x4.trans.shared.b16 {%0,%1,%2,%3}, [%4];"
                    : "=r"(bq[ni][0]), "=r"(bq[ni][1]), "=r"(bq[ni][2]), "=r"(bq[ni][3]) : "r"(addr));
            }
            #pragma unroll
            for (int mi = 0; mi < 2; ++mi)
                #pragma unroll
                for (int nj = 0; nj < 8; ++nj) {
                    uint32_t b0 = bq[nj >> 1][(nj & 1) * 2];
                    uint32_t b1 = bq[nj >> 1][(nj & 1) * 2 + 1];
                    asm volatile(
                        "mma.sync.aligned.m16n8k16.row.col.f32.bf16.bf16.f32 "
                        "{%0,%1,%2,%3}, {%4,%5,%6,%7}, {%8,%9}, {%0,%1,%2,%3};"
                        : "+f"(acc[mi][nj][0]), "+f"(acc[mi][nj][1]),
                          "+f"(acc[mi][nj][2]), "+f"(acc[mi][nj][3])
                        : "r"(a[mi][0]), "r"(a[mi][1]), "r"(a[mi][2]), "r"(a[mi][3]),
                          "r"(b0), "r"(b1));
                }
        }
    }

    int r_base = m0 + wm + (lane >> 2);
    int c_base = n0 + wn + (lane & 3) * 2;
    #pragma unroll
    for (int mi = 0; mi < 2; ++mi) {
        #pragma unroll
        for (int nj = 0; nj < 8; ++nj) {
            int r = r_base + mi * 16;
            int c = c_base + nj * 8;
            float bx = bias[c], by = bias[c + 1];
            float o00 = acc[mi][nj][0] + bx;
            float o01 = acc[mi][nj][1] + by;
            float o10 = acc[mi][nj][2] + bx;
            float o11 = acc[mi][nj][3] + by;
            if (EPI == 1) {
                o00 = gelu_f(o00); o01 = gelu_f(o01);
                o10 = gelu_f(o10); o11 = gelu_f(o11);
            }
            if (EPI == 2) {
                const float* rp0 = resid + (size_t)r * N + c;
                const float* rp1 = resid + (size_t)(r + 8) * N + c;
                float* Cf = (float*)Cp;
                float2 v0 = {o00 + rp0[0], o01 + rp0[1]};
                float2 v1 = {o10 + rp1[0], o11 + rp1[1]};
                *(float2*)(Cf + (size_t)r * N + c) = v0;
                *(float2*)(Cf + (size_t)(r + 8) * N + c) = v1;
            } else {
                bf16* Cb = (bf16*)Cp;
                __nv_bfloat162 v0 = {__float2bfloat16(o00), __float2bfloat16(o01)};
                __nv_bfloat162 v1 = {__float2bfloat16(o10), __float2bfloat16(o11)};
                *(__nv_bfloat162*)(Cb + (size_t)r * N + c) = v0;
                *(__nv_bfloat162*)(Cb + (size_t)(r + 8) * N + c) = v1;
            }
        }
    }
}

// ---------------- Deformable sampling: one warp = (token, head-pair) ---------
// lanes 0-15: head h0 (channel pair = lane), lanes 16-31: head h0+1.
__global__ void sample_kernel(const bf16* __restrict__ v, const float* __restrict__ offattn,
                              const float* __restrict__ rp, bf16* __restrict__ agg) {
    int gw = blockIdx.x * 8 + (threadIdx.x >> 5);
    int lane = threadIdx.x & 31;
    int tg = gw >> 2;                        // token
    int head = ((gw & 3) << 1) + (lane >> 4);
    int l16 = lane & 15;                     // channel-pair within head
    int bb = tg >> 13;
    int pos = tg & 8191;

    const float* lg = offattn + (size_t)tg * 256 + 144 + head * 9;
    float w[9];
    float mx = -1e30f;
    #pragma unroll
    for (int k = 0; k < 9; ++k) { w[k] = lg[k]; mx = fmaxf(mx, w[k]); }
    float sum = 0.f;
    #pragma unroll
    for (int k = 0; k < 9; ++k) { w[k] = expf(w[k] - mx); sum += w[k]; }
    float inv = 1.0f / sum;

    const float* rpp  = rp + (size_t)pos * 18;
    const float* offp = offattn + (size_t)tg * 256 + head * 18;
    const __nv_bfloat162* vc = (const __nv_bfloat162*)v + head * 16 + l16;
    int base = bb << 13;
    float a0 = 0.f, a1 = 0.f;
    #pragma unroll
    for (int k = 0; k < 9; ++k) {
        float cx = (rpp[k * 2 + 0] + offp[k * 2 + 0] + 1.0f) * 0.5f * 127.0f;
        float cy = (rpp[k * 2 + 1] + offp[k * 2 + 1] + 1.0f) * 0.5f * 63.0f;
        float fx = floorf(cx), fy = floorf(cy);
        float wx = cx - fx, wy = cy - fy;
        int x0 = min(max((int)fx, 0), 127);
        int x1 = min(max((int)fx + 1, 0), 127);
        int y0 = min(max((int)fy, 0), 63);
        int y1 = min(max((int)fy + 1, 0), 63);
        float2 v00 = __bfloat1622float2(vc[(size_t)(base + y0 * 128 + x0) * 128]);
        float2 v01 = __bfloat1622float2(vc[(size_t)(base + y0 * 128 + x1) * 128]);
        float2 v10 = __bfloat1622float2(vc[(size_t)(base + y1 * 128 + x0) * 128]);
        float2 v11 = __bfloat1622float2(vc[(size_t)(base + y1 * 128 + x1) * 128]);
        float w00 = (1.f - wy) * (1.f - wx), w01 = (1.f - wy) * wx;
        float w10 = wy * (1.f - wx),         w11 = wy * wx;
        float wk = w[k] * inv;
        a0 += (v00.x * w00 + v01.x * w01 + v10.x * w10 + v11.x * w11) * wk;
        a1 += (v00.y * w00 + v01.y * w01 + v10.y * w10 + v11.y * w11) * wk;
    }
    __nv_bfloat162 ov = {__float2bfloat16(a0), __float2bfloat16(a1)};
    *(__nv_bfloat162*)(agg + (size_t)tg * 256 + head * 32 + l16 * 2) = ov;
}

// ---------------- Depthwise 3x3 conv: sliding window, 4-way x-split ----------
__global__ void dwconv_kernel(const bf16* __restrict__ h, const float* __restrict__ wdw,
                              const float* __restrict__ bdw, bf16* __restrict__ o) {
    int c2 = blockIdx.x * 256 + threadIdx.x;
    int y = blockIdx.y & 63;
    int seg = blockIdx.y >> 6;
    int bb = blockIdx.z;
    int c = c2 * 2;
    int x0 = seg * 32;

    float w0[9], w1[9];
    #pragma unroll
    for (int i = 0; i < 9; ++i) { w0[i] = wdw[c * 9 + i]; w1[i] = wdw[(c + 1) * 9 + i]; }
    float bb0 = bdw[c], bb1 = bdw[c + 1];

    const __nv_bfloat162* hp = (const __nv_bfloat162*)h;
    size_t base = ((size_t)(bb << 13) + y * 128) * 512 + c2;
    bool hu = (y > 0), hd = (y < 63);
    __nv_bfloat162 zero = __float2bfloat162_rn(0.f);

    __nv_bfloat162 cm[3], cc[3], cn[3];
    {
        size_t p = base + ((x0 + 127) & 127) * 512;
        cm[0] = hu ? hp[p - 65536] : zero; cm[1] = hp[p]; cm[2] = hd ? hp[p + 65536] : zero;
        p = base + x0 * 512;
        cc[0] = hu ? hp[p - 65536] : zero; cc[1] = hp[p]; cc[2] = hd ? hp[p + 65536] : zero;
    }
    bf16* op = o + ((size_t)(bb << 13) + y * 128) * 1024 + c;

    for (int x = x0; x < x0 + 32; ++x) {
        size_t p = base + ((x + 1) & 127) * 512;
        cn[0] = hu ? hp[p - 65536] : zero; cn[1] = hp[p]; cn[2] = hd ? hp[p + 65536] : zero;

        float a0 = bb0, a1 = bb1;
        #pragma unroll
        for (int dy = 0; dy < 3; ++dy) {
            float2 vm = __bfloat1622float2(cm[dy]);
            float2 vc = __bfloat1622float2(cc[dy]);
            float2 vp = __bfloat1622float2(cn[dy]);
            a0 += vm.x * w0[dy * 3 + 0] + vc.x * w0[dy * 3 + 1] + vp.x * w0[dy * 3 + 2];
            a1 += vm.y * w1[dy * 3 + 0] + vc.y * w1[dy * 3 + 1] + vp.y * w1[dy * 3 + 2];
        }
        __nv_bfloat162 ov = {__float2bfloat16(gelu_f(a0)), __float2bfloat16(gelu_f(a1))};
        *(__nv_bfloat162*)(op + (size_t)x * 1024) = ov;

        #pragma unroll
        for (int i = 0; i < 3; ++i) { cm[i] = cc[i]; cc[i] = cn[i]; }
    }
}

// ---------------- launch ----------------
extern "C" void kernel_launch(void* const* d_in, const int* in_sizes, int n_in,
                              void* d_out, int out_size) {
    const float* x      = (const float*)d_in[0];
    const float* rp     = (const float*)d_in[1];
    const float* ln1_g  = (const float*)d_in[2];
    const float* ln1_b  = (const float*)d_in[3];
    const float* w_v    = (const float*)d_in[4];
    const float* b_v    = (const float*)d_in[5];
    const float* w_off  = (const float*)d_in[6];
    const float* b_off  = (const float*)d_in[7];
    const float* w_attn = (const float*)d_in[8];
    const float* b_attn = (const float*)d_in[9];
    const float* w_out  = (const float*)d_in[10];
    const float* b_out  = (const float*)d_in[11];
    const float* ln2_g  = (const float*)d_in[12];
    const float* ln2_b  = (const float*)d_in[13];
    const float* w1     = (const float*)d_in[14];
    const float* b1     = (const float*)d_in[15];
    const float* w_dw   = (const float*)d_in[16];
    const float* b_dw   = (const float*)d_in[17];
    const float* w2     = (const float*)d_in[18];
    const float* b2     = (const float*)d_in[19];
    float* out = (float*)d_out;

    float *xn, *offattn, *xres, *wcat, *bcat;
    bf16 *xnb, *vb, *aggb, *yb, *hb, *h2b, *wvb, *woutb, *w1b, *w2b;
    cudaGetSymbolAddress((void**)&xn,      g_xn);
    cudaGetSymbolAddress((void**)&offattn, g_offattn);
    cudaGetSymbolAddress((void**)&xres,    g_xres);
    cudaGetSymbolAddress((void**)&wcat,    g_wcat);
    cudaGetSymbolAddress((void**)&bcat,    g_bcat);
    cudaGetSymbolAddress((void**)&xnb,     g_xnb);
    cudaGetSymbolAddress((void**)&vb,      g_vb);
    cudaGetSymbolAddress((void**)&aggb,    g_aggb);
    cudaGetSymbolAddress((void**)&yb,      g_yb);
    cudaGetSymbolAddress((void**)&hb,      g_hb);
    cudaGetSymbolAddress((void**)&h2b,     g_h2b);
    cudaGetSymbolAddress((void**)&wvb,     g_wvb);
    cudaGetSymbolAddress((void**)&woutb,   g_woutb);
    cudaGetSymbolAddress((void**)&w1b,     g_w1b);
    cudaGetSymbolAddress((void**)&w2b,     g_w2b);

    cudaFuncSetAttribute(hgemm_kernel<0>, cudaFuncAttributeMaxDynamicSharedMemorySize, PSMEM);
    cudaFuncSetAttribute(hgemm_kernel<1>, cudaFuncAttributeMaxDynamicSharedMemorySize, PSMEM);
    cudaFuncSetAttribute(hgemm_kernel<2>, cudaFuncAttributeMaxDynamicSharedMemorySize, PSMEM);
    cudaFuncSetAttribute(tgemm_offattn,   cudaFuncAttributeMaxDynamicSharedMemorySize, TF_SMEM);

    // weight prep
    prep_kernel<<<(655360 + 65536 + 255) / 256, 256>>>(
        w_v, w_out, w1, w2, w_off, w_attn, b_off, b_attn,
        wvb, woutb, w1b, w2b, wcat, bcat);

    // 1. LN1 -> xn (tf32-rounded f32) + xnb (bf16)
    ln_kernel<true><<<NTOK, 256>>>(x, ln1_g, ln1_b, xn, xnb);
    // 2. v projection (bf16 TC)
    hgemm_kernel<0><<<dim3(256 / PBN, NTOK / PBM), 256, PSMEM>>>(xnb, wvb, b_v, nullptr, vb, 256, 256);
    // 3. offsets+attn combined (tf32 TC, no cvt)
    tgemm_offattn<<<NTOK / 64, 256, TF_SMEM>>>(xn, wcat, bcat, offattn);
    // 4. softmax + bilinear sampling + aggregation (head-pair warps)
    sample_kernel<<<NTOK / 2, 256>>>(vb, offattn, rp, aggb);
    // 5. output proj + residual -> xres (f32)
    hgemm_kernel<2><<<dim3(256 / PBN, NTOK / PBM), 256, PSMEM>>>(aggb, woutb, b_out, x, xres, 256, 256);
    // 6. LN2 -> yb (bf16)
    ln_kernel<false><<<NTOK, 256>>>(xres, ln2_g, ln2_b, nullptr, yb);
    // 7. fc1 + GELU (bf16 TC)
    hgemm_kernel<1><<<dim3(HID / PBN, NTOK / PBM), 256, PSMEM>>>(yb, w1b, b1, nullptr, hb, HID, 256);
    // 8. depthwise conv + GELU
    dwconv_kernel<<<dim3(2, 256, 2), 256>>>(hb, w_dw, b_dw, h2b);
    // 9. fc2 + residual -> out (f32)
    hgemm_kernel<2><<<dim3(256 / PBN, NTOK / PBM), 256, PSMEM>>>(h2b, w2b, b2, xres, out, 256, 1024);
}